// round 3
// baseline (speedup 1.0000x reference)
#include <cuda_runtime.h>

#define Bn 4
#define Ss 2048
#define Ee 1024
#define Hh 16
#define HD 64

// Scratch for Q,K,V in [b,h,s,d] layout (32 MB each). __device__ globals per
// allocation rules.
__device__ float g_Q[(size_t)Bn * Hh * Ss * HD];
__device__ float g_K[(size_t)Bn * Hh * Ss * HD];
__device__ float g_V[(size_t)Bn * Hh * Ss * HD];

// ---------------------------------------------------------------------------
// Projection GEMM: Out[b,h,s,d] = X[m,:] . W[n,:]   (y = x @ W^T)
// X: [8192, 1024] row-major, W: [1024, 1024] row-major (row n over k).
// 128x128 tile, BK=16, 256 threads, 8x8 per-thread micro-tile.
// ---------------------------------------------------------------------------
__global__ __launch_bounds__(256)
void proj_kernel(const float* __restrict__ X, const float* __restrict__ W, int which)
{
    float* __restrict__ Out = (which == 0) ? g_Q : (which == 1) ? g_K : g_V;

    __shared__ float As[16][128];   // [k][m]
    __shared__ float Bs[16][128];   // [k][n]

    const int t  = threadIdx.x;
    const int tx = t & 15;
    const int ty = t >> 4;
    const int m0 = blockIdx.y * 128;
    const int n0 = blockIdx.x * 128;

    float acc[8][8];
#pragma unroll
    for (int i = 0; i < 8; i++)
#pragma unroll
        for (int j = 0; j < 8; j++) acc[i][j] = 0.f;

    for (int k0 = 0; k0 < Ee; k0 += 16) {
        // Each tile: 128 rows x 16 k = 512 float4 loads, 2 per thread per matrix.
#pragma unroll
        for (int l = 0; l < 2; l++) {
            int idx = t + l * 256;
            int row = idx >> 2;
            int kc  = (idx & 3) << 2;
            float4 a = *reinterpret_cast<const float4*>(
                &X[(size_t)(m0 + row) * Ee + k0 + kc]);
            As[kc + 0][row] = a.x; As[kc + 1][row] = a.y;
            As[kc + 2][row] = a.z; As[kc + 3][row] = a.w;
            float4 b = *reinterpret_cast<const float4*>(
                &W[(size_t)(n0 + row) * Ee + k0 + kc]);
            Bs[kc + 0][row] = b.x; Bs[kc + 1][row] = b.y;
            Bs[kc + 2][row] = b.z; Bs[kc + 3][row] = b.w;
        }
        __syncthreads();

#pragma unroll
        for (int kk = 0; kk < 16; kk++) {
            float a[8], b[8];
            *(float4*)&a[0] = *(const float4*)&As[kk][ty * 8];
            *(float4*)&a[4] = *(const float4*)&As[kk][ty * 8 + 4];
            *(float4*)&b[0] = *(const float4*)&Bs[kk][tx * 8];
            *(float4*)&b[4] = *(const float4*)&Bs[kk][tx * 8 + 4];
#pragma unroll
            for (int i = 0; i < 8; i++)
#pragma unroll
                for (int j = 0; j < 8; j++)
                    acc[i][j] = fmaf(a[i], b[j], acc[i][j]);
        }
        __syncthreads();
    }

    // Store permuted to [b,h,s,d]. 8-col groups never cross a 64-wide head.
#pragma unroll
    for (int i = 0; i < 8; i++) {
        int m  = m0 + ty * 8 + i;
        int bb = m >> 11;
        int sr = m & 2047;
#pragma unroll
        for (int j = 0; j < 8; j += 4) {
            int n  = n0 + tx * 8 + j;
            int hh = n >> 6;
            int dd = n & 63;
            float4 v = make_float4(acc[i][j], acc[i][j + 1], acc[i][j + 2], acc[i][j + 3]);
            *reinterpret_cast<float4*>(
                &Out[((size_t)(bb * Hh + hh) * Ss + sr) * HD + dd]) = v;
        }
    }
}

// ---------------------------------------------------------------------------
// Flash attention per (b,h): 64-row Q tile per CTA, 64-key tiles, online
// softmax. 256 threads as 16x16; each thread owns a 4x4 sub-tile.
// Smem: Qs [d][q] (pre-scaled), KPs [d][k] reused as P [q][k], Vs [k][d].
// Exactly 48 KB static smem -> up to 4 CTAs/SM.
// ---------------------------------------------------------------------------
__global__ __launch_bounds__(256)
void attn_kernel(float* __restrict__ Out)
{
    __shared__ float Qs[64][64];   // [d][q], scaled by 1/32
    __shared__ float KPs[64][64];  // phase 1: K^T [d][k]; phase 2: P [q][k]
    __shared__ float Vs[64][64];   // [k][d]

    const int t  = threadIdx.x;
    const int tx = t & 15;
    const int ty = t >> 4;
    const int bh = blockIdx.y;            // b*16 + h
    const int q0 = blockIdx.x * 64;

    const float* __restrict__ Qbh = g_Q + (size_t)bh * Ss * HD;
    const float* __restrict__ Kbh = g_K + (size_t)bh * Ss * HD;
    const float* __restrict__ Vbh = g_V + (size_t)bh * Ss * HD;

    const float SCALE = 1.0f / 32.0f;     // 1/sqrt(EMBED_DIM=1024)

    // Load Q tile, transpose to [d][q], pre-scale.
#pragma unroll
    for (int l = 0; l < 4; l++) {
        int idx = t + l * 256;            // 0..1023
        int r   = idx >> 4;               // q row 0..63
        int dc  = (idx & 15) << 2;        // d col
        float4 v = *reinterpret_cast<const float4*>(&Qbh[(size_t)(q0 + r) * HD + dc]);
        Qs[dc + 0][r] = v.x * SCALE;
        Qs[dc + 1][r] = v.y * SCALE;
        Qs[dc + 2][r] = v.z * SCALE;
        Qs[dc + 3][r] = v.w * SCALE;
    }

    float m_i[4], l_i[4], o[4][4];
#pragma unroll
    for (int i = 0; i < 4; i++) {
        m_i[i] = -1e30f;
        l_i[i] = 0.f;
#pragma unroll
        for (int j = 0; j < 4; j++) o[i][j] = 0.f;
    }

    __syncthreads();

    for (int kt = 0; kt < Ss; kt += 64) {
        // Load K tile transposed [d][k] + V tile natural [k][d].
#pragma unroll
        for (int l = 0; l < 4; l++) {
            int idx = t + l * 256;
            int r   = idx >> 4;
            int dc  = (idx & 15) << 2;
            float4 kv = *reinterpret_cast<const float4*>(&Kbh[(size_t)(kt + r) * HD + dc]);
            KPs[dc + 0][r] = kv.x; KPs[dc + 1][r] = kv.y;
            KPs[dc + 2][r] = kv.z; KPs[dc + 3][r] = kv.w;
            *reinterpret_cast<float4*>(&Vs[r][dc]) =
                *reinterpret_cast<const float4*>(&Vbh[(size_t)(kt + r) * HD + dc]);
        }
        __syncthreads();

        // S = (Q/32) K^T : rows q = ty*4+i, cols k = tx*4+j
        float s[4][4];
#pragma unroll
        for (int i = 0; i < 4; i++)
#pragma unroll
            for (int j = 0; j < 4; j++) s[i][j] = 0.f;

#pragma unroll
        for (int d = 0; d < 64; d++) {
            float4 qv = *(const float4*)&Qs[d][ty * 4];
            float4 kv = *(const float4*)&KPs[d][tx * 4];
            const float qa[4] = {qv.x, qv.y, qv.z, qv.w};
            const float ka[4] = {kv.x, kv.y, kv.z, kv.w};
#pragma unroll
            for (int i = 0; i < 4; i++)
#pragma unroll
                for (int j = 0; j < 4; j++)
                    s[i][j] = fmaf(qa[i], ka[j], s[i][j]);
        }
        __syncthreads();   // all threads done reading KPs (K phase)

        // Online softmax. Row r is owned by the 16 threads sharing ty
        // (contiguous 16-lane shuffle group).
        float rmax[4], mn[4], alpha[4], rsum[4];
#pragma unroll
        for (int i = 0; i < 4; i++) {
            rmax[i] = fmaxf(fmaxf(s[i][0], s[i][1]), fmaxf(s[i][2], s[i][3]));
#pragma unroll
            for (int off = 8; off >= 1; off >>= 1)
                rmax[i] = fmaxf(rmax[i], __shfl_xor_sync(0xffffffffu, rmax[i], off, 16));
            mn[i]    = fmaxf(m_i[i], rmax[i]);
            alpha[i] = __expf(m_i[i] - mn[i]);
            m_i[i]   = mn[i];

            float rs = 0.f;
#pragma unroll
            for (int j = 0; j < 4; j++) {
                s[i][j] = __expf(s[i][j] - mn[i]);
                rs += s[i][j];
            }
#pragma unroll
            for (int off = 8; off >= 1; off >>= 1)
                rs += __shfl_xor_sync(0xffffffffu, rs, off, 16);
            rsum[i] = rs;

            l_i[i] = l_i[i] * alpha[i] + rsum[i];
#pragma unroll
            for (int j = 0; j < 4; j++) o[i][j] *= alpha[i];
        }

        // Write P into KPs as [q][k] (float4 rows, conflict-free).
#pragma unroll
        for (int i = 0; i < 4; i++)
            *(float4*)&KPs[ty * 4 + i][tx * 4] =
                make_float4(s[i][0], s[i][1], s[i][2], s[i][3]);
        __syncthreads();

        // O += P @ V : rows q = ty*4+i, cols d = tx*4+j
#pragma unroll
        for (int kk = 0; kk < 64; kk++) {
            float4 vv = *(const float4*)&Vs[kk][tx * 4];
            const float va[4] = {vv.x, vv.y, vv.z, vv.w};
            float p0 = KPs[ty * 4 + 0][kk];
            float p1 = KPs[ty * 4 + 1][kk];
            float p2 = KPs[ty * 4 + 2][kk];
            float p3 = KPs[ty * 4 + 3][kk];
#pragma unroll
            for (int j = 0; j < 4; j++) {
                o[0][j] = fmaf(p0, va[j], o[0][j]);
                o[1][j] = fmaf(p1, va[j], o[1][j]);
                o[2][j] = fmaf(p2, va[j], o[2][j]);
                o[3][j] = fmaf(p3, va[j], o[3][j]);
            }
        }
        __syncthreads();   // before overwriting KPs/Vs next tile
    }

    // Epilogue: normalize and store to [b, s, h*64+d] (== [B,S,E]).
    const int bb = bh >> 4;
    const int hh = bh & 15;
#pragma unroll
    for (int i = 0; i < 4; i++) {
        float inv = 1.0f / l_i[i];
        int srow = q0 + ty * 4 + i;
        float4 ov = make_float4(o[i][0] * inv, o[i][1] * inv,
                                o[i][2] * inv, o[i][3] * inv);
        *reinterpret_cast<float4*>(
            &Out[((size_t)(bb * Ss + srow)) * Ee + hh * 64 + tx * 4]) = ov;
    }
}

// ---------------------------------------------------------------------------
extern "C" void kernel_launch(void* const* d_in, const int* in_sizes, int n_in,
                              void* d_out, int out_size)
{
    const float* x  = (const float*)d_in[0];
    const float* Wq = (const float*)d_in[1];
    const float* Wk = (const float*)d_in[2];
    const float* Wv = (const float*)d_in[3];
    float* out = (float*)d_out;

    dim3 pgrid(Ee / 128, (Bn * Ss) / 128);   // (8, 64)
    proj_kernel<<<pgrid, 256>>>(x, Wq, 0);
    proj_kernel<<<pgrid, 256>>>(x, Wk, 1);
    proj_kernel<<<pgrid, 256>>>(x, Wv, 2);

    dim3 agrid(Ss / 64, Bn * Hh);            // (32, 64)
    attn_kernel<<<agrid, 256>>>(out);
}

// round 5
// speedup vs baseline: 1.3354x; 1.3354x over previous
#include <cuda_runtime.h>
#include <cuda_bf16.h>
#include <cstdint>

#define Bn 4
#define Ss 2048
#define Ee 1024
#define Hh 16
#define HD 64

// Scratch for Q,K,V in [b,h,s,d] layout. __device__ globals per allocation rules.
__device__ float g_Q[(size_t)Bn * Hh * Ss * HD];
__device__ float g_K[(size_t)Bn * Hh * Ss * HD];
__device__ float g_V[(size_t)Bn * Hh * Ss * HD];

// ===========================================================================
// Helpers
// ===========================================================================
__device__ __forceinline__ uint32_t smem_u32(const void* p) {
    uint32_t a;
    asm("{ .reg .u64 t; cvta.to.shared.u64 t, %1; cvt.u32.u64 %0, t; }"
        : "=r"(a) : "l"(p));
    return a;
}

__device__ __forceinline__ void ldm_x4(uint32_t addr, uint32_t& r0, uint32_t& r1,
                                       uint32_t& r2, uint32_t& r3) {
    asm volatile("ldmatrix.sync.aligned.m8n8.x4.shared.b16 {%0,%1,%2,%3}, [%4];"
                 : "=r"(r0), "=r"(r1), "=r"(r2), "=r"(r3) : "r"(addr));
}

__device__ __forceinline__ void mma16816(float* d, const uint32_t* a,
                                         uint32_t b0, uint32_t b1) {
    asm volatile(
        "mma.sync.aligned.m16n8k16.row.col.f32.bf16.bf16.f32 "
        "{%0,%1,%2,%3}, {%4,%5,%6,%7}, {%8,%9}, {%0,%1,%2,%3};"
        : "+f"(d[0]), "+f"(d[1]), "+f"(d[2]), "+f"(d[3])
        : "r"(a[0]), "r"(a[1]), "r"(a[2]), "r"(a[3]), "r"(b0), "r"(b1));
}

// fp32 pair -> bf16x2 hi + bf16x2 lo (residual)
__device__ __forceinline__ void split2(float x, float y, uint32_t& hi, uint32_t& lo) {
    __nv_bfloat162 h = __floats2bfloat162_rn(x, y);
    float2 f = __bfloat1622float2(h);
    __nv_bfloat162 l = __floats2bfloat162_rn(x - f.x, y - f.y);
    hi = *reinterpret_cast<uint32_t*>(&h);
    lo = *reinterpret_cast<uint32_t*>(&l);
}

// ===========================================================================
// Fused QKV projection via mma.sync bf16 hi/lo split.
// C[m,n] = sum_k X[m,k] * W[n,k]  (y = x @ W^T). Tile 128x128, BK=32.
// 8 warps: warp grid 4(m) x 2(n), each warp 32x64 (2x8 m16n8 atoms).
// Smem rows padded to 40 bf16 (80 B) -> conflict-free ldmatrix.
// ===========================================================================
#define BM 128
#define BN 128
#define BKp 32
#define LDA 40
#define NCH (Ee / BKp)   // 32

__global__ __launch_bounds__(256)
void proj_tc(const float* __restrict__ X, const float* __restrict__ Wq,
             const float* __restrict__ Wk, const float* __restrict__ Wv)
{
    __shared__ __nv_bfloat16 Ah[BM][LDA], Al[BM][LDA];
    __shared__ __nv_bfloat16 Bh[BN][LDA], Bl[BN][LDA];

    const int t    = threadIdx.x;
    const int wid  = t >> 5;
    const int lane = t & 31;
    const int n0   = blockIdx.x * BN;
    const int m0   = blockIdx.y * BM;
    const int z    = blockIdx.z;

    const float* __restrict__ W = (z == 0) ? Wq : (z == 1) ? Wk : Wv;
    float* __restrict__ Out     = (z == 0) ? g_Q : (z == 1) ? g_K : g_V;

    const int wm = (wid >> 1) * 32;   // warp m base within tile
    const int wn = (wid & 1) * 64;    // warp n base within tile

    const uint32_t aAh = smem_u32(Ah), aAl = smem_u32(Al);
    const uint32_t aBh = smem_u32(Bh), aBl = smem_u32(Bl);

    // ldmatrix lane address components (bytes)
    const int lr = lane & 7;
    // A tiles: 0:(m0-7,k0) 1:(m8-15,k0) 2:(m0-7,k8) 3:(m8-15,k8)
    const uint32_t aRowOff = (uint32_t)((lr + ((lane >> 3) & 1) * 8) * (LDA * 2)
                                        + (lane >> 4) * 16);
    // B tiles: 0:(n0-7,k0) 1:(n0-7,k8) 2:(n8-15,k0) 3:(n8-15,k8)
    const uint32_t bRowOff = (uint32_t)((lr + ((lane >> 4) & 1) * 8) * (LDA * 2)
                                        + ((lane >> 3) & 1) * 16);

    float acc[2][8][4];
#pragma unroll
    for (int i = 0; i < 2; i++)
#pragma unroll
        for (int j = 0; j < 8; j++)
#pragma unroll
            for (int v = 0; v < 4; v++) acc[i][j][v] = 0.f;

    // Loader mapping: float4 id -> (row, col)
    float4 pa[4], pb[4];
#pragma unroll
    for (int i = 0; i < 4; i++) {
        int f4 = t + i * 256;
        int row = f4 >> 3, col = (f4 & 7) * 4;
        pa[i] = *(const float4*)(X + (size_t)(m0 + row) * Ee + col);
        pb[i] = *(const float4*)(W + (size_t)(n0 + row) * Ee + col);
    }

    for (int c = 0; c < NCH; ++c) {
        // Store prefetched chunk to smem with hi/lo split.
#pragma unroll
        for (int i = 0; i < 4; i++) {
            int f4 = t + i * 256;
            int row = f4 >> 3, col = (f4 & 7) * 4;
            uint2 h, l;
            split2(pa[i].x, pa[i].y, h.x, l.x);
            split2(pa[i].z, pa[i].w, h.y, l.y);
            *(uint2*)&Ah[row][col] = h;
            *(uint2*)&Al[row][col] = l;
            split2(pb[i].x, pb[i].y, h.x, l.x);
            split2(pb[i].z, pb[i].w, h.y, l.y);
            *(uint2*)&Bh[row][col] = h;
            *(uint2*)&Bl[row][col] = l;
        }
        __syncthreads();

        // Prefetch next chunk (LDG latency overlaps HMMA below).
        if (c + 1 < NCH) {
            int k0 = (c + 1) * BKp;
#pragma unroll
            for (int i = 0; i < 4; i++) {
                int f4 = t + i * 256;
                int row = f4 >> 3, col = (f4 & 7) * 4;
                pa[i] = *(const float4*)(X + (size_t)(m0 + row) * Ee + k0 + col);
                pb[i] = *(const float4*)(W + (size_t)(n0 + row) * Ee + k0 + col);
            }
        }

        // Compute: 2 k16 steps per BK=32 chunk.
#pragma unroll
        for (int kt = 0; kt < 2; kt++) {
            const uint32_t kb = kt * 32;   // 16 bf16 = 32 bytes
            uint32_t ah[2][4], al[2][4], bh[4][4], bl[4][4];
#pragma unroll
            for (int mt = 0; mt < 2; mt++) {
                uint32_t ro = (uint32_t)((wm + mt * 16) * (LDA * 2)) + aRowOff + kb;
                ldm_x4(aAh + ro, ah[mt][0], ah[mt][1], ah[mt][2], ah[mt][3]);
                ldm_x4(aAl + ro, al[mt][0], al[mt][1], al[mt][2], al[mt][3]);
            }
#pragma unroll
            for (int nt4 = 0; nt4 < 4; nt4++) {
                uint32_t ro = (uint32_t)((wn + nt4 * 16) * (LDA * 2)) + bRowOff + kb;
                ldm_x4(aBh + ro, bh[nt4][0], bh[nt4][1], bh[nt4][2], bh[nt4][3]);
                ldm_x4(aBl + ro, bl[nt4][0], bl[nt4][1], bl[nt4][2], bl[nt4][3]);
            }
#pragma unroll
            for (int mt = 0; mt < 2; mt++)
#pragma unroll
                for (int nt = 0; nt < 8; nt++) {
                    uint32_t b0h = bh[nt >> 1][(nt & 1) * 2];
                    uint32_t b1h = bh[nt >> 1][(nt & 1) * 2 + 1];
                    uint32_t b0l = bl[nt >> 1][(nt & 1) * 2];
                    uint32_t b1l = bl[nt >> 1][(nt & 1) * 2 + 1];
                    mma16816(acc[mt][nt], ah[mt], b0h, b1h);
                    mma16816(acc[mt][nt], ah[mt], b0l, b1l);
                    mma16816(acc[mt][nt], al[mt], b0h, b1h);
                }
        }
        __syncthreads();
    }

    // Epilogue: fragment (c0,c1)=row g cols tc,tc+1; (c2,c3)=row g+8.
    const int g  = lane >> 2;
    const int tc = (lane & 3) * 2;
#pragma unroll
    for (int mt = 0; mt < 2; mt++) {
#pragma unroll
        for (int half = 0; half < 2; half++) {
            int m  = m0 + wm + mt * 16 + g + half * 8;
            int bb = m >> 11;
            int sr = m & 2047;
#pragma unroll
            for (int nt = 0; nt < 8; nt++) {
                int n  = n0 + wn + nt * 8 + tc;
                int hh = n >> 6;
                int dd = n & 63;
                float2 v = make_float2(acc[mt][nt][half * 2], acc[mt][nt][half * 2 + 1]);
                *(float2*)(Out + ((size_t)(bb * Hh + hh) * Ss + sr) * HD + dd) = v;
            }
        }
    }
}

// ---------------------------------------------------------------------------
// Flash attention per (b,h): unchanged (known-correct).
// ---------------------------------------------------------------------------
__global__ __launch_bounds__(256)
void attn_kernel(float* __restrict__ Out)
{
    __shared__ float Qs[64][64];   // [d][q], scaled by 1/32
    __shared__ float KPs[64][64];  // phase 1: K^T [d][k]; phase 2: P [q][k]
    __shared__ float Vs[64][64];   // [k][d]

    const int t  = threadIdx.x;
    const int tx = t & 15;
    const int ty = t >> 4;
    const int bh = blockIdx.y;
    const int q0 = blockIdx.x * 64;

    const float* __restrict__ Qbh = g_Q + (size_t)bh * Ss * HD;
    const float* __restrict__ Kbh = g_K + (size_t)bh * Ss * HD;
    const float* __restrict__ Vbh = g_V + (size_t)bh * Ss * HD;

    const float SCALE = 1.0f / 32.0f;

#pragma unroll
    for (int l = 0; l < 4; l++) {
        int idx = t + l * 256;
        int r   = idx >> 4;
        int dc  = (idx & 15) << 2;
        float4 v = *reinterpret_cast<const float4*>(&Qbh[(size_t)(q0 + r) * HD + dc]);
        Qs[dc + 0][r] = v.x * SCALE;
        Qs[dc + 1][r] = v.y * SCALE;
        Qs[dc + 2][r] = v.z * SCALE;
        Qs[dc + 3][r] = v.w * SCALE;
    }

    float m_i[4], l_i[4], o[4][4];
#pragma unroll
    for (int i = 0; i < 4; i++) {
        m_i[i] = -1e30f;
        l_i[i] = 0.f;
#pragma unroll
        for (int j = 0; j < 4; j++) o[i][j] = 0.f;
    }

    __syncthreads();

    for (int kt = 0; kt < Ss; kt += 64) {
#pragma unroll
        for (int l = 0; l < 4; l++) {
            int idx = t + l * 256;
            int r   = idx >> 4;
            int dc  = (idx & 15) << 2;
            float4 kv = *reinterpret_cast<const float4*>(&Kbh[(size_t)(kt + r) * HD + dc]);
            KPs[dc + 0][r] = kv.x; KPs[dc + 1][r] = kv.y;
            KPs[dc + 2][r] = kv.z; KPs[dc + 3][r] = kv.w;
            *reinterpret_cast<float4*>(&Vs[r][dc]) =
                *reinterpret_cast<const float4*>(&Vbh[(size_t)(kt + r) * HD + dc]);
        }
        __syncthreads();

        float s[4][4];
#pragma unroll
        for (int i = 0; i < 4; i++)
#pragma unroll
            for (int j = 0; j < 4; j++) s[i][j] = 0.f;

#pragma unroll
        for (int d = 0; d < 64; d++) {
            float4 qv = *(const float4*)&Qs[d][ty * 4];
            float4 kv = *(const float4*)&KPs[d][tx * 4];
            const float qa[4] = {qv.x, qv.y, qv.z, qv.w};
            const float ka[4] = {kv.x, kv.y, kv.z, kv.w};
#pragma unroll
            for (int i = 0; i < 4; i++)
#pragma unroll
                for (int j = 0; j < 4; j++)
                    s[i][j] = fmaf(qa[i], ka[j], s[i][j]);
        }
        __syncthreads();

        float rmax[4], mn[4], alpha[4], rsum[4];
#pragma unroll
        for (int i = 0; i < 4; i++) {
            rmax[i] = fmaxf(fmaxf(s[i][0], s[i][1]), fmaxf(s[i][2], s[i][3]));
#pragma unroll
            for (int off = 8; off >= 1; off >>= 1)
                rmax[i] = fmaxf(rmax[i], __shfl_xor_sync(0xffffffffu, rmax[i], off, 16));
            mn[i]    = fmaxf(m_i[i], rmax[i]);
            alpha[i] = __expf(m_i[i] - mn[i]);
            m_i[i]   = mn[i];

            float rs = 0.f;
#pragma unroll
            for (int j = 0; j < 4; j++) {
                s[i][j] = __expf(s[i][j] - mn[i]);
                rs += s[i][j];
            }
#pragma unroll
            for (int off = 8; off >= 1; off >>= 1)
                rs += __shfl_xor_sync(0xffffffffu, rs, off, 16);
            rsum[i] = rs;

            l_i[i] = l_i[i] * alpha[i] + rsum[i];
#pragma unroll
            for (int j = 0; j < 4; j++) o[i][j] *= alpha[i];
        }

#pragma unroll
        for (int i = 0; i < 4; i++)
            *(float4*)&KPs[ty * 4 + i][tx * 4] =
                make_float4(s[i][0], s[i][1], s[i][2], s[i][3]);
        __syncthreads();

#pragma unroll
        for (int kk = 0; kk < 64; kk++) {
            float4 vv = *(const float4*)&Vs[kk][tx * 4];
            const float va[4] = {vv.x, vv.y, vv.z, vv.w};
            float p0 = KPs[ty * 4 + 0][kk];
            float p1 = KPs[ty * 4 + 1][kk];
            float p2 = KPs[ty * 4 + 2][kk];
            float p3 = KPs[ty * 4 + 3][kk];
#pragma unroll
            for (int j = 0; j < 4; j++) {
                o[0][j] = fmaf(p0, va[j], o[0][j]);
                o[1][j] = fmaf(p1, va[j], o[1][j]);
                o[2][j] = fmaf(p2, va[j], o[2][j]);
                o[3][j] = fmaf(p3, va[j], o[3][j]);
            }
        }
        __syncthreads();
    }

    const int bb = bh >> 4;
    const int hh = bh & 15;
#pragma unroll
    for (int i = 0; i < 4; i++) {
        float inv = 1.0f / l_i[i];
        int srow = q0 + ty * 4 + i;
        float4 ov = make_float4(o[i][0] * inv, o[i][1] * inv,
                                o[i][2] * inv, o[i][3] * inv);
        *reinterpret_cast<float4*>(
            &Out[((size_t)(bb * Ss + srow)) * Ee + hh * 64 + tx * 4]) = ov;
    }
}

// ---------------------------------------------------------------------------
extern "C" void kernel_launch(void* const* d_in, const int* in_sizes, int n_in,
                              void* d_out, int out_size)
{
    const float* x  = (const float*)d_in[0];
    const float* Wq = (const float*)d_in[1];
    const float* Wk = (const float*)d_in[2];
    const float* Wv = (const float*)d_in[3];
    float* out = (float*)d_out;

    dim3 pgrid(Ee / BN, (Bn * Ss) / BM, 3);   // (8, 64, 3) — fused Q/K/V
    proj_tc<<<pgrid, 256>>>(x, Wq, Wk, Wv);

    dim3 agrid(Ss / 64, Bn * Hh);             // (32, 64)
    attn_kernel<<<agrid, 256>>>(out);
}

// round 6
// speedup vs baseline: 2.9567x; 2.2140x over previous
#include <cuda_runtime.h>
#include <cuda_bf16.h>
#include <cstdint>

#define Bn 4
#define Ss 2048
#define Ee 1024
#define Hh 16
#define HD 64

// Pre-split bf16 operands produced by the projection kernel.
// Q/K: [b,h,s,d]; V: transposed [b,h,d,s] (for PV's B operand).
__device__ __nv_bfloat16 g_Qh[(size_t)Bn * Hh * Ss * HD];
__device__ __nv_bfloat16 g_Ql[(size_t)Bn * Hh * Ss * HD];
__device__ __nv_bfloat16 g_Kh[(size_t)Bn * Hh * Ss * HD];
__device__ __nv_bfloat16 g_Kl[(size_t)Bn * Hh * Ss * HD];
__device__ __nv_bfloat16 g_Vth[(size_t)Bn * Hh * Ss * HD];
__device__ __nv_bfloat16 g_Vtl[(size_t)Bn * Hh * Ss * HD];

// ===========================================================================
// Helpers
// ===========================================================================
__device__ __forceinline__ uint32_t smem_u32(const void* p) {
    uint32_t a;
    asm("{ .reg .u64 t; cvta.to.shared.u64 t, %1; cvt.u32.u64 %0, t; }"
        : "=r"(a) : "l"(p));
    return a;
}

__device__ __forceinline__ void ldm_x4(uint32_t addr, uint32_t& r0, uint32_t& r1,
                                       uint32_t& r2, uint32_t& r3) {
    asm volatile("ldmatrix.sync.aligned.m8n8.x4.shared.b16 {%0,%1,%2,%3}, [%4];"
                 : "=r"(r0), "=r"(r1), "=r"(r2), "=r"(r3) : "r"(addr));
}

__device__ __forceinline__ void mma16816(float* d, const uint32_t* a,
                                         uint32_t b0, uint32_t b1) {
    asm volatile(
        "mma.sync.aligned.m16n8k16.row.col.f32.bf16.bf16.f32 "
        "{%0,%1,%2,%3}, {%4,%5,%6,%7}, {%8,%9}, {%0,%1,%2,%3};"
        : "+f"(d[0]), "+f"(d[1]), "+f"(d[2]), "+f"(d[3])
        : "r"(a[0]), "r"(a[1]), "r"(a[2]), "r"(a[3]), "r"(b0), "r"(b1));
}

// fp32 pair -> bf16x2 hi + bf16x2 lo (residual)
__device__ __forceinline__ void split2(float x, float y, uint32_t& hi, uint32_t& lo) {
    __nv_bfloat162 h = __floats2bfloat162_rn(x, y);
    float2 f = __bfloat1622float2(h);
    __nv_bfloat162 l = __floats2bfloat162_rn(x - f.x, y - f.y);
    hi = *reinterpret_cast<uint32_t*>(&h);
    lo = *reinterpret_cast<uint32_t*>(&l);
}

__device__ __forceinline__ void splitf(float x, __nv_bfloat16& h, __nv_bfloat16& l) {
    h = __float2bfloat16(x);
    l = __float2bfloat16(x - __bfloat162float(h));
}

// ===========================================================================
// Fused QKV projection via mma.sync bf16 hi/lo split (validated R4).
// Writes pre-split bf16 hi/lo outputs; Q pre-scaled by 1/32; V transposed.
// ===========================================================================
#define BM 128
#define BN 128
#define BKp 32
#define LDA 40
#define NCH (Ee / BKp)   // 32

__global__ __launch_bounds__(256)
void proj_tc(const float* __restrict__ X, const float* __restrict__ Wq,
             const float* __restrict__ Wk, const float* __restrict__ Wv)
{
    __shared__ __nv_bfloat16 Ah[BM][LDA], Al[BM][LDA];
    __shared__ __nv_bfloat16 Bh[BN][LDA], Bl[BN][LDA];

    const int t    = threadIdx.x;
    const int wid  = t >> 5;
    const int lane = t & 31;
    const int n0   = blockIdx.x * BN;
    const int m0   = blockIdx.y * BM;
    const int z    = blockIdx.z;

    const float* __restrict__ W = (z == 0) ? Wq : (z == 1) ? Wk : Wv;

    const int wm = (wid >> 1) * 32;
    const int wn = (wid & 1) * 64;

    const uint32_t aAh = smem_u32(Ah), aAl = smem_u32(Al);
    const uint32_t aBh = smem_u32(Bh), aBl = smem_u32(Bl);

    const int lr = lane & 7;
    const uint32_t aRowOff = (uint32_t)((lr + ((lane >> 3) & 1) * 8) * (LDA * 2)
                                        + (lane >> 4) * 16);
    const uint32_t bRowOff = (uint32_t)((lr + ((lane >> 4) & 1) * 8) * (LDA * 2)
                                        + ((lane >> 3) & 1) * 16);

    float acc[2][8][4];
#pragma unroll
    for (int i = 0; i < 2; i++)
#pragma unroll
        for (int j = 0; j < 8; j++)
#pragma unroll
            for (int v = 0; v < 4; v++) acc[i][j][v] = 0.f;

    float4 pa[4], pb[4];
#pragma unroll
    for (int i = 0; i < 4; i++) {
        int f4 = t + i * 256;
        int row = f4 >> 3, col = (f4 & 7) * 4;
        pa[i] = *(const float4*)(X + (size_t)(m0 + row) * Ee + col);
        pb[i] = *(const float4*)(W + (size_t)(n0 + row) * Ee + col);
    }

    for (int c = 0; c < NCH; ++c) {
#pragma unroll
        for (int i = 0; i < 4; i++) {
            int f4 = t + i * 256;
            int row = f4 >> 3, col = (f4 & 7) * 4;
            uint2 h, l;
            split2(pa[i].x, pa[i].y, h.x, l.x);
            split2(pa[i].z, pa[i].w, h.y, l.y);
            *(uint2*)&Ah[row][col] = h;
            *(uint2*)&Al[row][col] = l;
            split2(pb[i].x, pb[i].y, h.x, l.x);
            split2(pb[i].z, pb[i].w, h.y, l.y);
            *(uint2*)&Bh[row][col] = h;
            *(uint2*)&Bl[row][col] = l;
        }
        __syncthreads();

        if (c + 1 < NCH) {
            int k0 = (c + 1) * BKp;
#pragma unroll
            for (int i = 0; i < 4; i++) {
                int f4 = t + i * 256;
                int row = f4 >> 3, col = (f4 & 7) * 4;
                pa[i] = *(const float4*)(X + (size_t)(m0 + row) * Ee + k0 + col);
                pb[i] = *(const float4*)(W + (size_t)(n0 + row) * Ee + k0 + col);
            }
        }

#pragma unroll
        for (int kt = 0; kt < 2; kt++) {
            const uint32_t kb = kt * 32;
            uint32_t ah[2][4], al[2][4], bh[4][4], bl[4][4];
#pragma unroll
            for (int mt = 0; mt < 2; mt++) {
                uint32_t ro = (uint32_t)((wm + mt * 16) * (LDA * 2)) + aRowOff + kb;
                ldm_x4(aAh + ro, ah[mt][0], ah[mt][1], ah[mt][2], ah[mt][3]);
                ldm_x4(aAl + ro, al[mt][0], al[mt][1], al[mt][2], al[mt][3]);
            }
#pragma unroll
            for (int nt4 = 0; nt4 < 4; nt4++) {
                uint32_t ro = (uint32_t)((wn + nt4 * 16) * (LDA * 2)) + bRowOff + kb;
                ldm_x4(aBh + ro, bh[nt4][0], bh[nt4][1], bh[nt4][2], bh[nt4][3]);
                ldm_x4(aBl + ro, bl[nt4][0], bl[nt4][1], bl[nt4][2], bl[nt4][3]);
            }
#pragma unroll
            for (int mt = 0; mt < 2; mt++)
#pragma unroll
                for (int nt = 0; nt < 8; nt++) {
                    uint32_t b0h = bh[nt >> 1][(nt & 1) * 2];
                    uint32_t b1h = bh[nt >> 1][(nt & 1) * 2 + 1];
                    uint32_t b0l = bl[nt >> 1][(nt & 1) * 2];
                    uint32_t b1l = bl[nt >> 1][(nt & 1) * 2 + 1];
                    mma16816(acc[mt][nt], ah[mt], b0h, b1h);
                    mma16816(acc[mt][nt], ah[mt], b0l, b1l);
                    mma16816(acc[mt][nt], al[mt], b0h, b1h);
                }
        }
        __syncthreads();
    }

    // Epilogue: split to bf16 hi/lo. Q scaled by 1/32; V stored transposed.
    const int g  = lane >> 2;
    const int tc = (lane & 3) * 2;
    const float scl = (z == 0) ? (1.0f / 32.0f) : 1.0f;
#pragma unroll
    for (int mt = 0; mt < 2; mt++) {
#pragma unroll
        for (int half = 0; half < 2; half++) {
            int m  = m0 + wm + mt * 16 + g + half * 8;
            int bb = m >> 11;
            int sq = m & 2047;
#pragma unroll
            for (int nt = 0; nt < 8; nt++) {
                int n  = n0 + wn + nt * 8 + tc;
                int hh = n >> 6;
                int dd = n & 63;
                float v0 = acc[mt][nt][half * 2] * scl;
                float v1 = acc[mt][nt][half * 2 + 1] * scl;
                if (z == 2) {
                    size_t vb = (size_t)(bb * Hh + hh) * HD * Ss;
                    __nv_bfloat16 h0, l0, h1, l1;
                    splitf(v0, h0, l0);
                    splitf(v1, h1, l1);
                    g_Vth[vb + (size_t)dd * Ss + sq]       = h0;
                    g_Vtl[vb + (size_t)dd * Ss + sq]       = l0;
                    g_Vth[vb + (size_t)(dd + 1) * Ss + sq] = h1;
                    g_Vtl[vb + (size_t)(dd + 1) * Ss + sq] = l1;
                } else {
                    uint32_t hi, lo;
                    split2(v0, v1, hi, lo);
                    size_t off = ((size_t)(bb * Hh + hh) * Ss + sq) * HD + dd;
                    __nv_bfloat16* ph = (z == 0) ? g_Qh : g_Kh;
                    __nv_bfloat16* pl = (z == 0) ? g_Ql : g_Kl;
                    *reinterpret_cast<uint32_t*>(ph + off) = hi;
                    *reinterpret_cast<uint32_t*>(pl + off) = lo;
                }
            }
        }
    }
}

// ===========================================================================
// Tensor-core flash attention. 1 CTA = 128 q-rows of one (b,h). 8 warps,
// each owns 16 full rows (warp-local softmax). 64-key tiles.
// QK^T: 3-term hi/lo split MMA; PV: 3-term split; P passed in registers.
// Smem (36864 B union): phase Q = Qh|Ql staging (2x18432);
//                       phase KV = Kh|Kl|Vth|Vtl (4x9216). Rows 144 B.
// ===========================================================================
__global__ __launch_bounds__(256, 1)
void attn_tc(float* __restrict__ Out)
{
    __shared__ __align__(16) char smch[36864];

    const int t    = threadIdx.x;
    const int wid  = t >> 5;
    const int lane = t & 31;
    const int bh   = blockIdx.y;
    const int q0   = blockIdx.x * 128;

    const uint32_t smb = smem_u32(smch);
    const int lr = lane & 7;
    const uint32_t aOff = (uint32_t)((lr + ((lane >> 3) & 1) * 8) * 144
                                     + (lane >> 4) * 16);
    const uint32_t bOff = (uint32_t)((lr + ((lane >> 4) & 1) * 8) * 144
                                     + ((lane >> 3) & 1) * 16);

    // ---- Phase 1: stage Q tile (128x64 hi/lo), extract A-fragments ----
    {
        const uint4* __restrict__ qhg = reinterpret_cast<const uint4*>(g_Qh);
        const uint4* __restrict__ qlg = reinterpret_cast<const uint4*>(g_Ql);
        uint4* s4 = reinterpret_cast<uint4*>(smch);
#pragma unroll
        for (int i = 0; i < 4; i++) {
            int idx = t + i * 256;            // 0..1023
            int row = idx >> 3;
            int c8  = idx & 7;
            size_t src = (size_t)(bh * Ss + q0 + row) * 8 + c8;
            s4[(row * 144 + c8 * 16) >> 4]           = qhg[src];
            s4[(18432 + row * 144 + c8 * 16) >> 4]   = qlg[src];
        }
    }
    __syncthreads();

    uint32_t qh[4][4], ql[4][4];
#pragma unroll
    for (int kt2 = 0; kt2 < 4; kt2++) {
        uint32_t ad = smb + (uint32_t)(wid * 16 * 144) + aOff + kt2 * 32;
        ldm_x4(ad,          qh[kt2][0], qh[kt2][1], qh[kt2][2], qh[kt2][3]);
        ldm_x4(ad + 18432,  ql[kt2][0], ql[kt2][1], ql[kt2][2], ql[kt2][3]);
    }
    __syncthreads();   // smem now free for K/V

    float o[8][4];
#pragma unroll
    for (int j = 0; j < 8; j++)
#pragma unroll
        for (int v = 0; v < 4; v++) o[j][v] = 0.f;
    float m0r = -1e30f, m1r = -1e30f, l0r = 0.f, l1r = 0.f;

    const uint4* __restrict__ khg = reinterpret_cast<const uint4*>(g_Kh);
    const uint4* __restrict__ klg = reinterpret_cast<const uint4*>(g_Kl);
    const uint4* __restrict__ vhg = reinterpret_cast<const uint4*>(g_Vth);
    const uint4* __restrict__ vlg = reinterpret_cast<const uint4*>(g_Vtl);
    uint4* s4 = reinterpret_cast<uint4*>(smch);

    for (int kt = 0; kt < Ss; kt += 64) {
        // ---- Load K (hi/lo) + Vt (hi/lo) tiles, 64 rows x 64 bf16 each ----
#pragma unroll
        for (int i = 0; i < 2; i++) {
            int idx = t + i * 256;            // 0..511
            int row = idx >> 3;
            int c8  = idx & 7;
            uint32_t dst = (uint32_t)(row * 144 + c8 * 16) >> 4;
            size_t ks = (size_t)(bh * Ss + kt + row) * 8 + c8;
            size_t vs = (size_t)(bh * HD + row) * (Ss / 8) + (kt >> 3) + c8;
            s4[dst]                 = khg[ks];
            s4[dst + (9216 >> 4)]   = klg[ks];
            s4[dst + (18432 >> 4)]  = vhg[vs];
            s4[dst + (27648 >> 4)]  = vlg[vs];
        }
        __syncthreads();

        // ---- S = Qs . K^T  (3-term split) ----
        float s[8][4];
#pragma unroll
        for (int j = 0; j < 8; j++)
#pragma unroll
            for (int v = 0; v < 4; v++) s[j][v] = 0.f;

#pragma unroll
        for (int ks2 = 0; ks2 < 4; ks2++) {
            uint32_t kh[4][4], kl_[4][4];
#pragma unroll
            for (int u = 0; u < 4; u++) {
                uint32_t ad = smb + (uint32_t)(u * 16 * 144) + bOff + ks2 * 32;
                ldm_x4(ad,        kh[u][0], kh[u][1], kh[u][2], kh[u][3]);
                ldm_x4(ad + 9216, kl_[u][0], kl_[u][1], kl_[u][2], kl_[u][3]);
            }
#pragma unroll
            for (int j = 0; j < 8; j++) {
                int u = j >> 1, od = (j & 1) * 2;
                mma16816(s[j], qh[ks2], kh[u][od], kh[u][od + 1]);
                mma16816(s[j], qh[ks2], kl_[u][od], kl_[u][od + 1]);
                mma16816(s[j], ql[ks2], kh[u][od], kh[u][od + 1]);
            }
        }

        // ---- Online softmax (warp-local; rows g and g+8 per thread) ----
        float rmx0 = -1e30f, rmx1 = -1e30f;
#pragma unroll
        for (int j = 0; j < 8; j++) {
            rmx0 = fmaxf(rmx0, fmaxf(s[j][0], s[j][1]));
            rmx1 = fmaxf(rmx1, fmaxf(s[j][2], s[j][3]));
        }
        rmx0 = fmaxf(rmx0, __shfl_xor_sync(0xffffffffu, rmx0, 1));
        rmx0 = fmaxf(rmx0, __shfl_xor_sync(0xffffffffu, rmx0, 2));
        rmx1 = fmaxf(rmx1, __shfl_xor_sync(0xffffffffu, rmx1, 1));
        rmx1 = fmaxf(rmx1, __shfl_xor_sync(0xffffffffu, rmx1, 2));

        float mn0 = fmaxf(m0r, rmx0), mn1 = fmaxf(m1r, rmx1);
        float a0 = __expf(m0r - mn0), a1 = __expf(m1r - mn1);
        m0r = mn0; m1r = mn1;

        float rs0 = 0.f, rs1 = 0.f;
#pragma unroll
        for (int j = 0; j < 8; j++) {
            s[j][0] = __expf(s[j][0] - mn0);
            s[j][1] = __expf(s[j][1] - mn0);
            s[j][2] = __expf(s[j][2] - mn1);
            s[j][3] = __expf(s[j][3] - mn1);
            rs0 += s[j][0] + s[j][1];
            rs1 += s[j][2] + s[j][3];
        }
        rs0 += __shfl_xor_sync(0xffffffffu, rs0, 1);
        rs0 += __shfl_xor_sync(0xffffffffu, rs0, 2);
        rs1 += __shfl_xor_sync(0xffffffffu, rs1, 1);
        rs1 += __shfl_xor_sync(0xffffffffu, rs1, 2);
        l0r = l0r * a0 + rs0;
        l1r = l1r * a1 + rs1;
#pragma unroll
        for (int j = 0; j < 8; j++) {
            o[j][0] *= a0; o[j][1] *= a0;
            o[j][2] *= a1; o[j][3] *= a1;
        }

        // ---- Pack P into A-fragments (registers; C-layout == A-layout) ----
        uint32_t ph[4][4], pl_[4][4];
#pragma unroll
        for (int ks2 = 0; ks2 < 4; ks2++) {
            int j0 = 2 * ks2, j1 = 2 * ks2 + 1;
            split2(s[j0][0], s[j0][1], ph[ks2][0], pl_[ks2][0]);
            split2(s[j0][2], s[j0][3], ph[ks2][1], pl_[ks2][1]);
            split2(s[j1][0], s[j1][1], ph[ks2][2], pl_[ks2][2]);
            split2(s[j1][2], s[j1][3], ph[ks2][3], pl_[ks2][3]);
        }

        // ---- O += P . V  (3-term split; B = Vt rows d, k = keys) ----
#pragma unroll
        for (int ks2 = 0; ks2 < 4; ks2++) {
            uint32_t vh[4][4], vl_[4][4];
#pragma unroll
            for (int u = 0; u < 4; u++) {
                uint32_t ad = smb + 18432 + (uint32_t)(u * 16 * 144) + bOff + ks2 * 32;
                ldm_x4(ad,        vh[u][0], vh[u][1], vh[u][2], vh[u][3]);
                ldm_x4(ad + 9216, vl_[u][0], vl_[u][1], vl_[u][2], vl_[u][3]);
            }
#pragma unroll
            for (int j = 0; j < 8; j++) {
                int u = j >> 1, od = (j & 1) * 2;
                mma16816(o[j], ph[ks2], vh[u][od], vh[u][od + 1]);
                mma16816(o[j], pl_[ks2], vh[u][od], vh[u][od + 1]);
                mma16816(o[j], ph[ks2], vl_[u][od], vl_[u][od + 1]);
            }
        }
        __syncthreads();   // before next tile overwrites smem
    }

    // ---- Epilogue: normalize, store to [b, s, h*64+d] ----
    const int g  = lane >> 2;
    const int tc = (lane & 3) * 2;
    const int bb = bh >> 4;
    const int hh = bh & 15;
    const float i0 = 1.0f / l0r, i1 = 1.0f / l1r;
    const int q  = q0 + wid * 16 + g;
#pragma unroll
    for (int j = 0; j < 8; j++) {
        int d = j * 8 + tc;
        size_t off0 = ((size_t)(bb * Ss + q)) * Ee + hh * 64 + d;
        size_t off1 = ((size_t)(bb * Ss + q + 8)) * Ee + hh * 64 + d;
        *(float2*)(Out + off0) = make_float2(o[j][0] * i0, o[j][1] * i0);
        *(float2*)(Out + off1) = make_float2(o[j][2] * i1, o[j][3] * i1);
    }
}

// ---------------------------------------------------------------------------
extern "C" void kernel_launch(void* const* d_in, const int* in_sizes, int n_in,
                              void* d_out, int out_size)
{
    const float* x  = (const float*)d_in[0];
    const float* Wq = (const float*)d_in[1];
    const float* Wk = (const float*)d_in[2];
    const float* Wv = (const float*)d_in[3];
    float* out = (float*)d_out;

    dim3 pgrid(Ee / BN, (Bn * Ss) / BM, 3);   // (8, 64, 3) — fused Q/K/V
    proj_tc<<<pgrid, 256>>>(x, Wq, Wk, Wv);

    dim3 agrid(Ss / 128, Bn * Hh);            // (16, 64)
    attn_tc<<<agrid, 256>>>(out);
}

// round 8
// speedup vs baseline: 3.3938x; 1.1478x over previous
#include <cuda_runtime.h>
#include <cuda_bf16.h>
#include <cstdint>

#define Bn 4
#define Ss 2048
#define Ee 1024
#define Hh 16
#define HD 64

// Pre-split bf16 inputs (filled by split_xw)
__device__ __align__(16) __nv_bfloat16 g_Xh[(size_t)Bn * Ss * Ee];
__device__ __align__(16) __nv_bfloat16 g_Xl[(size_t)Bn * Ss * Ee];
__device__ __align__(16) __nv_bfloat16 g_Wh[(size_t)3 * Ee * Ee];
__device__ __align__(16) __nv_bfloat16 g_Wl[(size_t)3 * Ee * Ee];

// Pre-split bf16 Q/K/V produced by the projection (Q pre-scaled by 1/32).
// Q/K: [b,h,s,d]; V transposed: [b,h,d,s].
__device__ __align__(16) __nv_bfloat16 g_Qh[(size_t)Bn * Hh * Ss * HD];
__device__ __align__(16) __nv_bfloat16 g_Ql[(size_t)Bn * Hh * Ss * HD];
__device__ __align__(16) __nv_bfloat16 g_Kh[(size_t)Bn * Hh * Ss * HD];
__device__ __align__(16) __nv_bfloat16 g_Kl[(size_t)Bn * Hh * Ss * HD];
__device__ __align__(16) __nv_bfloat16 g_Vth[(size_t)Bn * Hh * Ss * HD];
__device__ __align__(16) __nv_bfloat16 g_Vtl[(size_t)Bn * Hh * Ss * HD];

// ===========================================================================
// Helpers
// ===========================================================================
__device__ __forceinline__ uint32_t smem_u32(const void* p) {
    uint32_t a;
    asm("{ .reg .u64 t; cvta.to.shared.u64 t, %1; cvt.u32.u64 %0, t; }"
        : "=r"(a) : "l"(p));
    return a;
}

__device__ __forceinline__ void ldm_x4(uint32_t addr, uint32_t& r0, uint32_t& r1,
                                       uint32_t& r2, uint32_t& r3) {
    asm volatile("ldmatrix.sync.aligned.m8n8.x4.shared.b16 {%0,%1,%2,%3}, [%4];"
                 : "=r"(r0), "=r"(r1), "=r"(r2), "=r"(r3) : "r"(addr));
}

__device__ __forceinline__ void mma16816(float* d, const uint32_t* a,
                                         uint32_t b0, uint32_t b1) {
    asm volatile(
        "mma.sync.aligned.m16n8k16.row.col.f32.bf16.bf16.f32 "
        "{%0,%1,%2,%3}, {%4,%5,%6,%7}, {%8,%9}, {%0,%1,%2,%3};"
        : "+f"(d[0]), "+f"(d[1]), "+f"(d[2]), "+f"(d[3])
        : "r"(a[0]), "r"(a[1]), "r"(a[2]), "r"(a[3]), "r"(b0), "r"(b1));
}

__device__ __forceinline__ void cpa16(uint32_t dst, const void* src) {
    asm volatile("cp.async.cg.shared.global [%0], [%1], 16;"
                 :: "r"(dst), "l"(src) : "memory");
}
#define CP_COMMIT() asm volatile("cp.async.commit_group;" ::: "memory")
#define CP_WAIT0()  asm volatile("cp.async.wait_group 0;" ::: "memory")
#define CP_WAIT1()  asm volatile("cp.async.wait_group 1;" ::: "memory")

// fp32 pair -> bf16x2 hi + bf16x2 lo (residual)
__device__ __forceinline__ void split2(float x, float y, uint32_t& hi, uint32_t& lo) {
    __nv_bfloat162 h = __floats2bfloat162_rn(x, y);
    float2 f = __bfloat1622float2(h);
    __nv_bfloat162 l = __floats2bfloat162_rn(x - f.x, y - f.y);
    hi = *reinterpret_cast<uint32_t*>(&h);
    lo = *reinterpret_cast<uint32_t*>(&l);
}

__device__ __forceinline__ void splitf(float x, __nv_bfloat16& h, __nv_bfloat16& l) {
    h = __float2bfloat16(x);
    l = __float2bfloat16(x - __bfloat162float(h));
}

// ===========================================================================
// Pre-pass: split X and W into bf16 hi/lo. Bandwidth-bound, ~25 us.
// ===========================================================================
__global__ void split_xw(const float* __restrict__ x, const float* __restrict__ wq,
                         const float* __restrict__ wk, const float* __restrict__ wv)
{
    const int XN2 = (Bn * Ss * Ee) / 2;   // float2 count in X
    const int WN2 = (Ee * Ee) / 2;        // float2 count per W
    const int total = XN2 + 3 * WN2;
    for (int i = blockIdx.x * blockDim.x + threadIdx.x; i < total;
         i += gridDim.x * blockDim.x) {
        float2 v;
        uint32_t hi, lo;
        if (i < XN2) {
            v = reinterpret_cast<const float2*>(x)[i];
            split2(v.x, v.y, hi, lo);
            reinterpret_cast<uint32_t*>(g_Xh)[i] = hi;
            reinterpret_cast<uint32_t*>(g_Xl)[i] = lo;
        } else {
            int r = i - XN2;
            int w = r / WN2;
            int j = r - w * WN2;
            const float* src = (w == 0) ? wq : (w == 1) ? wk : wv;
            v = reinterpret_cast<const float2*>(src)[j];
            split2(v.x, v.y, hi, lo);
            reinterpret_cast<uint32_t*>(g_Wh)[r] = hi;
            reinterpret_cast<uint32_t*>(g_Wl)[r] = lo;
        }
    }
}

// ===========================================================================
// Fused QKV projection: pre-split bf16 operands, cp.async double-buffered.
// C[m,n] = sum_k X[m,k] W[n,k]. Tile 128x128, BK=64, 16 chunks.
// Smem: 2 stages x 4 sections (Ah,Al,Bh,Bl), each 128 rows x 144 B.
// 8 warps: 4(m) x 2(n), each 32x64 out (2x8 m16n8 atoms), 3-term split.
// ===========================================================================
#define SECB 18432            // 128 * 144
#define STGB (4 * SECB)       // 73728
#define PROJ_SMEM (2 * STGB)  // 147456
#define NCHP 16               // 1024 / 64

__global__ __launch_bounds__(256, 1)
void proj_tc()
{
    extern __shared__ __align__(16) char sm[];
    const int t    = threadIdx.x;
    const int wid  = t >> 5;
    const int lane = t & 31;
    const int n0   = blockIdx.x * 128;
    const int m0   = blockIdx.y * 128;
    const int z    = blockIdx.z;

    const __nv_bfloat16* __restrict__ Wh = g_Wh + (size_t)z * Ee * Ee;
    const __nv_bfloat16* __restrict__ Wl = g_Wl + (size_t)z * Ee * Ee;

    const int wm = (wid >> 1) * 32;
    const int wn = (wid & 1) * 64;
    const uint32_t smb = smem_u32(sm);

    const int lr = lane & 7;
    const uint32_t aRowOff = (uint32_t)((lr + ((lane >> 3) & 1) * 8) * 144
                                        + (lane >> 4) * 16);
    const uint32_t bRowOff = (uint32_t)((lr + ((lane >> 4) & 1) * 8) * 144
                                        + ((lane >> 3) & 1) * 16);

    float acc[2][8][4];
#pragma unroll
    for (int i = 0; i < 2; i++)
#pragma unroll
        for (int j = 0; j < 8; j++)
#pragma unroll
            for (int v = 0; v < 4; v++) acc[i][j][v] = 0.f;

    // Issue one chunk's loads: 4 sections x 128 rows x 8 x 16B = 16/thread.
    auto issue_chunk = [&](int c, int stg) {
        const int k0 = c * 64;
        const uint32_t base = smb + stg * STGB;
#pragma unroll
        for (int j = 0; j < 16; j++) {
            int gi  = t + j * 256;         // 0..4095
            int sec = gi >> 10;
            int idx = gi & 1023;
            int row = idx >> 3;
            int c8  = idx & 7;
            uint32_t dst = base + sec * SECB + row * 144 + c8 * 16;
            const __nv_bfloat16* src;
            if (sec == 0)      src = g_Xh + (size_t)(m0 + row) * Ee + k0 + c8 * 8;
            else if (sec == 1) src = g_Xl + (size_t)(m0 + row) * Ee + k0 + c8 * 8;
            else if (sec == 2) src = Wh + (size_t)(n0 + row) * Ee + k0 + c8 * 8;
            else               src = Wl + (size_t)(n0 + row) * Ee + k0 + c8 * 8;
            cpa16(dst, src);
        }
        CP_COMMIT();
    };

    issue_chunk(0, 0);

    for (int c = 0; c < NCHP; ++c) {
        const int cur = c & 1;
        if (c + 1 < NCHP) { issue_chunk(c + 1, 1 - cur); CP_WAIT1(); }
        else              { CP_WAIT0(); }
        __syncthreads();

        const uint32_t sb = smb + cur * STGB;
#pragma unroll
        for (int kt = 0; kt < 4; kt++) {
            const uint32_t kb = kt * 32;
            uint32_t ah[2][4], al[2][4], bh[4][4], bl[4][4];
#pragma unroll
            for (int mt = 0; mt < 2; mt++) {
                uint32_t ro = sb + (uint32_t)((wm + mt * 16) * 144) + aRowOff + kb;
                ldm_x4(ro,        ah[mt][0], ah[mt][1], ah[mt][2], ah[mt][3]);
                ldm_x4(ro + SECB, al[mt][0], al[mt][1], al[mt][2], al[mt][3]);
            }
#pragma unroll
            for (int u = 0; u < 4; u++) {
                uint32_t ro = sb + 2 * SECB + (uint32_t)((wn + u * 16) * 144)
                              + bRowOff + kb;
                ldm_x4(ro,        bh[u][0], bh[u][1], bh[u][2], bh[u][3]);
                ldm_x4(ro + SECB, bl[u][0], bl[u][1], bl[u][2], bl[u][3]);
            }
#pragma unroll
            for (int mt = 0; mt < 2; mt++)
#pragma unroll
                for (int nt = 0; nt < 8; nt++) {
                    uint32_t b0h = bh[nt >> 1][(nt & 1) * 2];
                    uint32_t b1h = bh[nt >> 1][(nt & 1) * 2 + 1];
                    uint32_t b0l = bl[nt >> 1][(nt & 1) * 2];
                    uint32_t b1l = bl[nt >> 1][(nt & 1) * 2 + 1];
                    mma16816(acc[mt][nt], ah[mt], b0h, b1h);
                    mma16816(acc[mt][nt], ah[mt], b0l, b1l);
                    mma16816(acc[mt][nt], al[mt], b0h, b1h);
                }
        }
        __syncthreads();
    }

    // Epilogue: split to bf16 hi/lo. Q scaled by 1/32; V stored transposed.
    const int g  = lane >> 2;
    const int tc = (lane & 3) * 2;
    const float scl = (z == 0) ? (1.0f / 32.0f) : 1.0f;
#pragma unroll
    for (int mt = 0; mt < 2; mt++) {
#pragma unroll
        for (int half = 0; half < 2; half++) {
            int m  = m0 + wm + mt * 16 + g + half * 8;
            int bb = m >> 11;
            int sq = m & 2047;
#pragma unroll
            for (int nt = 0; nt < 8; nt++) {
                int n  = n0 + wn + nt * 8 + tc;
                int hh = n >> 6;
                int dd = n & 63;
                float v0 = acc[mt][nt][half * 2] * scl;
                float v1 = acc[mt][nt][half * 2 + 1] * scl;
                if (z == 2) {
                    size_t vb = (size_t)(bb * Hh + hh) * HD * Ss;
                    __nv_bfloat16 h0, l0, h1, l1;
                    splitf(v0, h0, l0);
                    splitf(v1, h1, l1);
                    g_Vth[vb + (size_t)dd * Ss + sq]       = h0;
                    g_Vtl[vb + (size_t)dd * Ss + sq]       = l0;
                    g_Vth[vb + (size_t)(dd + 1) * Ss + sq] = h1;
                    g_Vtl[vb + (size_t)(dd + 1) * Ss + sq] = l1;
                } else {
                    uint32_t hi, lo;
                    split2(v0, v1, hi, lo);
                    size_t off = ((size_t)(bb * Hh + hh) * Ss + sq) * HD + dd;
                    __nv_bfloat16* ph = (z == 0) ? g_Qh : g_Kh;
                    __nv_bfloat16* pl = (z == 0) ? g_Ql : g_Kl;
                    *reinterpret_cast<uint32_t*>(ph + off) = hi;
                    *reinterpret_cast<uint32_t*>(pl + off) = lo;
                }
            }
        }
    }
}

// ===========================================================================
// Tensor-core flash attention with cp.async double-buffered K/V tiles.
// 1 CTA = 128 q-rows of one (b,h); 8 warps x 16 rows (warp-local softmax).
// Buffers: 2 x (Kh|Kl|Vth|Vtl), each section 64 rows x 144 B (9216).
// Q staged once into buf0, fragments extracted, then KV pipeline runs.
// ===========================================================================
#define ASEC 9216
#define ABUF (4 * ASEC)          // 36864
#define ATTN_SMEM (2 * ABUF)     // 73728
#define NKT (Ss / 64)            // 32

__global__ __launch_bounds__(256, 1)
void attn_tc(float* __restrict__ Out)
{
    extern __shared__ __align__(16) char sma[];
    const int t    = threadIdx.x;
    const int wid  = t >> 5;
    const int lane = t & 31;
    const int bh   = blockIdx.y;
    const int q0   = blockIdx.x * 128;

    const uint32_t smb = smem_u32(sma);
    const int lr = lane & 7;
    const uint32_t aOff = (uint32_t)((lr + ((lane >> 3) & 1) * 8) * 144
                                     + (lane >> 4) * 16);
    const uint32_t bOff = (uint32_t)((lr + ((lane >> 4) & 1) * 8) * 144
                                     + ((lane >> 3) & 1) * 16);

    // ---- Stage Q tile (128x64 hi/lo) into buf0 via cp.async ----
#pragma unroll
    for (int j = 0; j < 8; j++) {
        int gi   = t + j * 256;          // 0..2047
        int half = gi >> 10;             // 0 = hi, 1 = lo
        int idx  = gi & 1023;
        int row  = idx >> 3;
        int c8   = idx & 7;
        const __nv_bfloat16* src =
            (half ? g_Ql : g_Qh) + (size_t)(bh * Ss + q0 + row) * HD + c8 * 8;
        cpa16(smb + half * (2 * ASEC) + row * 144 + c8 * 16, src);
    }
    CP_COMMIT();
    CP_WAIT0();
    __syncthreads();

    uint32_t qh[4][4], ql[4][4];
#pragma unroll
    for (int kt2 = 0; kt2 < 4; kt2++) {
        uint32_t ad = smb + (uint32_t)(wid * 16 * 144) + aOff + kt2 * 32;
        ldm_x4(ad,             qh[kt2][0], qh[kt2][1], qh[kt2][2], qh[kt2][3]);
        ldm_x4(ad + 2 * ASEC,  ql[kt2][0], ql[kt2][1], ql[kt2][2], ql[kt2][3]);
    }
    __syncthreads();   // buf0 free for KV

    float o[8][4];
#pragma unroll
    for (int j = 0; j < 8; j++)
#pragma unroll
        for (int v = 0; v < 4; v++) o[j][v] = 0.f;
    float m0r = -1e30f, m1r = -1e30f, l0r = 0.f, l1r = 0.f;

    // Issue one KV tile: 4 sections x 64 rows x 8 x 16B = 8/thread.
    auto issue_tile = [&](int kt, int buf) {
        const uint32_t base = smb + buf * ABUF;
#pragma unroll
        for (int j = 0; j < 8; j++) {
            int gi  = t + j * 256;       // 0..2047
            int sec = gi >> 9;           // 0..3
            int idx = gi & 511;
            int row = idx >> 3;
            int c8  = idx & 7;
            const __nv_bfloat16* src;
            if (sec == 0)      src = g_Kh  + (size_t)(bh * Ss + kt + row) * HD + c8 * 8;
            else if (sec == 1) src = g_Kl  + (size_t)(bh * Ss + kt + row) * HD + c8 * 8;
            else if (sec == 2) src = g_Vth + (size_t)(bh * HD + row) * Ss + kt + c8 * 8;
            else               src = g_Vtl + (size_t)(bh * HD + row) * Ss + kt + c8 * 8;
            cpa16(base + sec * ASEC + row * 144 + c8 * 16, src);
        }
        CP_COMMIT();
    };

    issue_tile(0, 0);

    for (int ti = 0; ti < NKT; ti++) {
        const int cur = ti & 1;
        if (ti + 1 < NKT) { issue_tile((ti + 1) * 64, 1 - cur); CP_WAIT1(); }
        else              { CP_WAIT0(); }
        __syncthreads();

        const uint32_t bb = smb + cur * ABUF;

        // ---- S = Qs . K^T  (3-term split) ----
        float s[8][4];
#pragma unroll
        for (int j = 0; j < 8; j++)
#pragma unroll
            for (int v = 0; v < 4; v++) s[j][v] = 0.f;

#pragma unroll
        for (int ks2 = 0; ks2 < 4; ks2++) {
            uint32_t kh[4][4], kl_[4][4];
#pragma unroll
            for (int u = 0; u < 4; u++) {
                uint32_t ad = bb + (uint32_t)(u * 16 * 144) + bOff + ks2 * 32;
                ldm_x4(ad,        kh[u][0], kh[u][1], kh[u][2], kh[u][3]);
                ldm_x4(ad + ASEC, kl_[u][0], kl_[u][1], kl_[u][2], kl_[u][3]);
            }
#pragma unroll
            for (int j = 0; j < 8; j++) {
                int u = j >> 1, od = (j & 1) * 2;
                mma16816(s[j], qh[ks2], kh[u][od], kh[u][od + 1]);
                mma16816(s[j], qh[ks2], kl_[u][od], kl_[u][od + 1]);
                mma16816(s[j], ql[ks2], kh[u][od], kh[u][od + 1]);
            }
        }

        // ---- Online softmax (warp-local) ----
        float rmx0 = -1e30f, rmx1 = -1e30f;
#pragma unroll
        for (int j = 0; j < 8; j++) {
            rmx0 = fmaxf(rmx0, fmaxf(s[j][0], s[j][1]));
            rmx1 = fmaxf(rmx1, fmaxf(s[j][2], s[j][3]));
        }
        rmx0 = fmaxf(rmx0, __shfl_xor_sync(0xffffffffu, rmx0, 1));
        rmx0 = fmaxf(rmx0, __shfl_xor_sync(0xffffffffu, rmx0, 2));
        rmx1 = fmaxf(rmx1, __shfl_xor_sync(0xffffffffu, rmx1, 1));
        rmx1 = fmaxf(rmx1, __shfl_xor_sync(0xffffffffu, rmx1, 2));

        float mn0 = fmaxf(m0r, rmx0), mn1 = fmaxf(m1r, rmx1);
        float a0 = __expf(m0r - mn0), a1 = __expf(m1r - mn1);
        m0r = mn0; m1r = mn1;

        float rs0 = 0.f, rs1 = 0.f;
#pragma unroll
        for (int j = 0; j < 8; j++) {
            s[j][0] = __expf(s[j][0] - mn0);
            s[j][1] = __expf(s[j][1] - mn0);
            s[j][2] = __expf(s[j][2] - mn1);
            s[j][3] = __expf(s[j][3] - mn1);
            rs0 += s[j][0] + s[j][1];
            rs1 += s[j][2] + s[j][3];
        }
        rs0 += __shfl_xor_sync(0xffffffffu, rs0, 1);
        rs0 += __shfl_xor_sync(0xffffffffu, rs0, 2);
        rs1 += __shfl_xor_sync(0xffffffffu, rs1, 1);
        rs1 += __shfl_xor_sync(0xffffffffu, rs1, 2);
        l0r = l0r * a0 + rs0;
        l1r = l1r * a1 + rs1;
#pragma unroll
        for (int j = 0; j < 8; j++) {
            o[j][0] *= a0; o[j][1] *= a0;
            o[j][2] *= a1; o[j][3] *= a1;
        }

        // ---- Pack P into A-fragments (registers) ----
        uint32_t ph[4][4], pl_[4][4];
#pragma unroll
        for (int ks2 = 0; ks2 < 4; ks2++) {
            int j0 = 2 * ks2, j1 = 2 * ks2 + 1;
            split2(s[j0][0], s[j0][1], ph[ks2][0], pl_[ks2][0]);
            split2(s[j0][2], s[j0][3], ph[ks2][1], pl_[ks2][1]);
            split2(s[j1][0], s[j1][1], ph[ks2][2], pl_[ks2][2]);
            split2(s[j1][2], s[j1][3], ph[ks2][3], pl_[ks2][3]);
        }

        // ---- O += P . V  (3-term split) ----
#pragma unroll
        for (int ks2 = 0; ks2 < 4; ks2++) {
            uint32_t vh[4][4], vl_[4][4];
#pragma unroll
            for (int u = 0; u < 4; u++) {
                uint32_t ad = bb + 2 * ASEC + (uint32_t)(u * 16 * 144) + bOff + ks2 * 32;
                ldm_x4(ad,        vh[u][0], vh[u][1], vh[u][2], vh[u][3]);
                ldm_x4(ad + ASEC, vl_[u][0], vl_[u][1], vl_[u][2], vl_[u][3]);
            }
#pragma unroll
            for (int j = 0; j < 8; j++) {
                int u = j >> 1, od = (j & 1) * 2;
                mma16816(o[j], ph[ks2], vh[u][od], vh[u][od + 1]);
                mma16816(o[j], pl_[ks2], vh[u][od], vh[u][od + 1]);
                mma16816(o[j], ph[ks2], vl_[u][od], vl_[u][od + 1]);
            }
        }
        __syncthreads();   // next issue overwrites buf[1-cur]
    }

    // ---- Epilogue ----
    const int g  = lane >> 2;
    const int tc = (lane & 3) * 2;
    const int bb2 = bh >> 4;
    const int hh  = bh & 15;
    const float i0 = 1.0f / l0r, i1 = 1.0f / l1r;
    const int q  = q0 + wid * 16 + g;
#pragma unroll
    for (int j = 0; j < 8; j++) {
        int d = j * 8 + tc;
        size_t off0 = ((size_t)(bb2 * Ss + q)) * Ee + hh * 64 + d;
        size_t off1 = ((size_t)(bb2 * Ss + q + 8)) * Ee + hh * 64 + d;
        *(float2*)(Out + off0) = make_float2(o[j][0] * i0, o[j][1] * i0);
        *(float2*)(Out + off1) = make_float2(o[j][2] * i1, o[j][3] * i1);
    }
}

// ---------------------------------------------------------------------------
extern "C" void kernel_launch(void* const* d_in, const int* in_sizes, int n_in,
                              void* d_out, int out_size)
{
    const float* x  = (const float*)d_in[0];
    const float* Wq = (const float*)d_in[1];
    const float* Wk = (const float*)d_in[2];
    const float* Wv = (const float*)d_in[3];
    float* out = (float*)d_out;

    static bool attr_done = false;
    if (!attr_done) {
        cudaFuncSetAttribute(proj_tc, cudaFuncAttributeMaxDynamicSharedMemorySize,
                             PROJ_SMEM);
        cudaFuncSetAttribute(attn_tc, cudaFuncAttributeMaxDynamicSharedMemorySize,
                             ATTN_SMEM);
        attr_done = true;
    }

    split_xw<<<2048, 256>>>(x, Wq, Wk, Wv);

    dim3 pgrid(Ee / 128, (Bn * Ss) / 128, 3);   // (8, 64, 3)
    proj_tc<<<pgrid, 256, PROJ_SMEM>>>();

    dim3 agrid(Ss / 128, Bn * Hh);              // (16, 64)
    attn_tc<<<agrid, 256, ATTN_SMEM>>>(out);
}

// round 10
// speedup vs baseline: 3.5086x; 1.0338x over previous
#include <cuda_runtime.h>
#include <cuda_bf16.h>
#include <cstdint>

#define Bn 4
#define Ss 2048
#define Ee 1024
#define Hh 16
#define HD 64

// Pre-split bf16 inputs (filled by split_xw)
__device__ __align__(16) __nv_bfloat16 g_Xh[(size_t)Bn * Ss * Ee];
__device__ __align__(16) __nv_bfloat16 g_Xl[(size_t)Bn * Ss * Ee];
__device__ __align__(16) __nv_bfloat16 g_Wh[(size_t)3 * Ee * Ee];
__device__ __align__(16) __nv_bfloat16 g_Wl[(size_t)3 * Ee * Ee];

// Pre-split bf16 Q/K/V (Q pre-scaled by 1/32). Q/K: [b,h,s,d]; V: [b,h,d,s].
__device__ __align__(16) __nv_bfloat16 g_Qh[(size_t)Bn * Hh * Ss * HD];
__device__ __align__(16) __nv_bfloat16 g_Ql[(size_t)Bn * Hh * Ss * HD];
__device__ __align__(16) __nv_bfloat16 g_Kh[(size_t)Bn * Hh * Ss * HD];
__device__ __align__(16) __nv_bfloat16 g_Kl[(size_t)Bn * Hh * Ss * HD];
__device__ __align__(16) __nv_bfloat16 g_Vth[(size_t)Bn * Hh * Ss * HD];
__device__ __align__(16) __nv_bfloat16 g_Vtl[(size_t)Bn * Hh * Ss * HD];

// ===========================================================================
// Helpers
// ===========================================================================
__device__ __forceinline__ uint32_t smem_u32(const void* p) {
    uint32_t a;
    asm("{ .reg .u64 t; cvta.to.shared.u64 t, %1; cvt.u32.u64 %0, t; }"
        : "=r"(a) : "l"(p));
    return a;
}

__device__ __forceinline__ void ldm_x4(uint32_t addr, uint32_t& r0, uint32_t& r1,
                                       uint32_t& r2, uint32_t& r3) {
    asm volatile("ldmatrix.sync.aligned.m8n8.x4.shared.b16 {%0,%1,%2,%3}, [%4];"
                 : "=r"(r0), "=r"(r1), "=r"(r2), "=r"(r3) : "r"(addr));
}

__device__ __forceinline__ void mma16816(float* d, const uint32_t* a,
                                         uint32_t b0, uint32_t b1) {
    asm volatile(
        "mma.sync.aligned.m16n8k16.row.col.f32.bf16.bf16.f32 "
        "{%0,%1,%2,%3}, {%4,%5,%6,%7}, {%8,%9}, {%0,%1,%2,%3};"
        : "+f"(d[0]), "+f"(d[1]), "+f"(d[2]), "+f"(d[3])
        : "r"(a[0]), "r"(a[1]), "r"(a[2]), "r"(a[3]), "r"(b0), "r"(b1));
}

__device__ __forceinline__ void cpa16(uint32_t dst, const void* src) {
    asm volatile("cp.async.cg.shared.global [%0], [%1], 16;"
                 :: "r"(dst), "l"(src) : "memory");
}
#define CP_COMMIT() asm volatile("cp.async.commit_group;" ::: "memory")
#define CP_WAIT0()  asm volatile("cp.async.wait_group 0;" ::: "memory")
#define CP_WAIT1()  asm volatile("cp.async.wait_group 1;" ::: "memory")

__device__ __forceinline__ float ex2f(float x) {
    float r;
    asm("ex2.approx.ftz.f32 %0, %1;" : "=f"(r) : "f"(x));
    return r;
}

// fp32 pair -> bf16x2 hi (round-nearest) + bf16x2 lo (residual)
__device__ __forceinline__ void split2(float x, float y, uint32_t& hi, uint32_t& lo) {
    __nv_bfloat162 h = __floats2bfloat162_rn(x, y);
    float2 f = __bfloat1622float2(h);
    __nv_bfloat162 l = __floats2bfloat162_rn(x - f.x, y - f.y);
    hi = *reinterpret_cast<uint32_t*>(&h);
    lo = *reinterpret_cast<uint32_t*>(&l);
}

// Cheap truncation split: Ph = mantissa-truncated bf16 (exact residual in fp32).
__device__ __forceinline__ void splitP(float x, float y, uint32_t& hi, uint32_t& lo) {
    uint32_t bx = __float_as_uint(x) & 0xFFFF0000u;
    uint32_t by = __float_as_uint(y) & 0xFFFF0000u;
    uint32_t h;
    asm("prmt.b32 %0, %1, %2, 0x7632;" : "=r"(h) : "r"(bx), "r"(by));
    float rx = x - __uint_as_float(bx);
    float ry = y - __uint_as_float(by);
    __nv_bfloat162 l = __floats2bfloat162_rn(rx, ry);
    hi = h;
    lo = *reinterpret_cast<uint32_t*>(&l);
}

__device__ __forceinline__ void splitf(float x, __nv_bfloat16& h, __nv_bfloat16& l) {
    h = __float2bfloat16(x);
    l = __float2bfloat16(x - __bfloat162float(h));
}

// ===========================================================================
// Pre-pass: split X and W into bf16 hi/lo (~18 us, bandwidth-bound).
// ===========================================================================
__global__ void split_xw(const float* __restrict__ x, const float* __restrict__ wq,
                         const float* __restrict__ wk, const float* __restrict__ wv)
{
    const int XN2 = (Bn * Ss * Ee) / 2;
    const int WN2 = (Ee * Ee) / 2;
    const int total = XN2 + 3 * WN2;
    for (int i = blockIdx.x * blockDim.x + threadIdx.x; i < total;
         i += gridDim.x * blockDim.x) {
        float2 v;
        uint32_t hi, lo;
        if (i < XN2) {
            v = reinterpret_cast<const float2*>(x)[i];
            split2(v.x, v.y, hi, lo);
            reinterpret_cast<uint32_t*>(g_Xh)[i] = hi;
            reinterpret_cast<uint32_t*>(g_Xl)[i] = lo;
        } else {
            int r = i - XN2;
            int w = r / WN2;
            int j = r - w * WN2;
            const float* src = (w == 0) ? wq : (w == 1) ? wk : wv;
            v = reinterpret_cast<const float2*>(src)[j];
            split2(v.x, v.y, hi, lo);
            reinterpret_cast<uint32_t*>(g_Wh)[r] = hi;
            reinterpret_cast<uint32_t*>(g_Wl)[r] = lo;
        }
    }
}

// ===========================================================================
// Fused QKV projection (unchanged from R7): cp.async double-buffered,
// tile 128x128, BK=64, 8 warps, 3-term bf16 split.
// ===========================================================================
#define SECB 18432
#define STGB (4 * SECB)
#define PROJ_SMEM (2 * STGB)
#define NCHP 16

__global__ __launch_bounds__(256, 1)
void proj_tc()
{
    extern __shared__ __align__(16) char sm[];
    const int t    = threadIdx.x;
    const int wid  = t >> 5;
    const int lane = t & 31;
    const int n0   = blockIdx.x * 128;
    const int m0   = blockIdx.y * 128;
    const int z    = blockIdx.z;

    const __nv_bfloat16* __restrict__ Wh = g_Wh + (size_t)z * Ee * Ee;
    const __nv_bfloat16* __restrict__ Wl = g_Wl + (size_t)z * Ee * Ee;

    const int wm = (wid >> 1) * 32;
    const int wn = (wid & 1) * 64;
    const uint32_t smb = smem_u32(sm);

    const int lr = lane & 7;
    const uint32_t aRowOff = (uint32_t)((lr + ((lane >> 3) & 1) * 8) * 144
                                        + (lane >> 4) * 16);
    const uint32_t bRowOff = (uint32_t)((lr + ((lane >> 4) & 1) * 8) * 144
                                        + ((lane >> 3) & 1) * 16);

    float acc[2][8][4];
#pragma unroll
    for (int i = 0; i < 2; i++)
#pragma unroll
        for (int j = 0; j < 8; j++)
#pragma unroll
            for (int v = 0; v < 4; v++) acc[i][j][v] = 0.f;

    auto issue_chunk = [&](int c, int stg) {
        const int k0 = c * 64;
        const uint32_t base = smb + stg * STGB;
#pragma unroll
        for (int j = 0; j < 16; j++) {
            int gi  = t + j * 256;
            int sec = gi >> 10;
            int idx = gi & 1023;
            int row = idx >> 3;
            int c8  = idx & 7;
            uint32_t dst = base + sec * SECB + row * 144 + c8 * 16;
            const __nv_bfloat16* src;
            if (sec == 0)      src = g_Xh + (size_t)(m0 + row) * Ee + k0 + c8 * 8;
            else if (sec == 1) src = g_Xl + (size_t)(m0 + row) * Ee + k0 + c8 * 8;
            else if (sec == 2) src = Wh + (size_t)(n0 + row) * Ee + k0 + c8 * 8;
            else               src = Wl + (size_t)(n0 + row) * Ee + k0 + c8 * 8;
            cpa16(dst, src);
        }
        CP_COMMIT();
    };

    issue_chunk(0, 0);

    for (int c = 0; c < NCHP; ++c) {
        const int cur = c & 1;
        if (c + 1 < NCHP) { issue_chunk(c + 1, 1 - cur); CP_WAIT1(); }
        else              { CP_WAIT0(); }
        __syncthreads();

        const uint32_t sb = smb + cur * STGB;
#pragma unroll
        for (int kt = 0; kt < 4; kt++) {
            const uint32_t kb = kt * 32;
            uint32_t ah[2][4], al[2][4], bh[4][4], bl[4][4];
#pragma unroll
            for (int mt = 0; mt < 2; mt++) {
                uint32_t ro = sb + (uint32_t)((wm + mt * 16) * 144) + aRowOff + kb;
                ldm_x4(ro,        ah[mt][0], ah[mt][1], ah[mt][2], ah[mt][3]);
                ldm_x4(ro + SECB, al[mt][0], al[mt][1], al[mt][2], al[mt][3]);
            }
#pragma unroll
            for (int u = 0; u < 4; u++) {
                uint32_t ro = sb + 2 * SECB + (uint32_t)((wn + u * 16) * 144)
                              + bRowOff + kb;
                ldm_x4(ro,        bh[u][0], bh[u][1], bh[u][2], bh[u][3]);
                ldm_x4(ro + SECB, bl[u][0], bl[u][1], bl[u][2], bl[u][3]);
            }
#pragma unroll
            for (int mt = 0; mt < 2; mt++)
#pragma unroll
                for (int nt = 0; nt < 8; nt++) {
                    uint32_t b0h = bh[nt >> 1][(nt & 1) * 2];
                    uint32_t b1h = bh[nt >> 1][(nt & 1) * 2 + 1];
                    uint32_t b0l = bl[nt >> 1][(nt & 1) * 2];
                    uint32_t b1l = bl[nt >> 1][(nt & 1) * 2 + 1];
                    mma16816(acc[mt][nt], ah[mt], b0h, b1h);
                    mma16816(acc[mt][nt], ah[mt], b0l, b1l);
                    mma16816(acc[mt][nt], al[mt], b0h, b1h);
                }
        }
        __syncthreads();
    }

    const int g  = lane >> 2;
    const int tc = (lane & 3) * 2;
    const float scl = (z == 0) ? (1.0f / 32.0f) : 1.0f;
#pragma unroll
    for (int mt = 0; mt < 2; mt++) {
#pragma unroll
        for (int half = 0; half < 2; half++) {
            int m  = m0 + wm + mt * 16 + g + half * 8;
            int bb = m >> 11;
            int sq = m & 2047;
#pragma unroll
            for (int nt = 0; nt < 8; nt++) {
                int n  = n0 + wn + nt * 8 + tc;
                int hh = n >> 6;
                int dd = n & 63;
                float v0 = acc[mt][nt][half * 2] * scl;
                float v1 = acc[mt][nt][half * 2 + 1] * scl;
                if (z == 2) {
                    size_t vb = (size_t)(bb * Hh + hh) * HD * Ss;
                    __nv_bfloat16 h0, l0, h1, l1;
                    splitf(v0, h0, l0);
                    splitf(v1, h1, l1);
                    g_Vth[vb + (size_t)dd * Ss + sq]       = h0;
                    g_Vtl[vb + (size_t)dd * Ss + sq]       = l0;
                    g_Vth[vb + (size_t)(dd + 1) * Ss + sq] = h1;
                    g_Vtl[vb + (size_t)(dd + 1) * Ss + sq] = l1;
                } else {
                    uint32_t hi, lo;
                    split2(v0, v1, hi, lo);
                    size_t off = ((size_t)(bb * Hh + hh) * Ss + sq) * HD + dd;
                    __nv_bfloat16* ph = (z == 0) ? g_Qh : g_Kh;
                    __nv_bfloat16* pl = (z == 0) ? g_Ql : g_Kl;
                    *reinterpret_cast<uint32_t*>(ph + off) = hi;
                    *reinterpret_cast<uint32_t*>(pl + off) = lo;
                }
            }
        }
    }
}

// ===========================================================================
// Tensor-core flash attention, 128-thread CTAs for 3 CTAs/SM.
// 1 CTA = 64 q-rows of one (b,h); 4 warps x 16 rows (warp-local softmax).
// Per-warp compute identical to R7. cp.async double-buffered K/V.
// ===========================================================================
#define ASEC 9216
#define ABUF (4 * ASEC)          // 36864
#define ATTN_SMEM (2 * ABUF)     // 73728
#define NKT (Ss / 64)            // 32

__global__ __launch_bounds__(128, 3)
void attn_tc(float* __restrict__ Out)
{
    extern __shared__ __align__(16) char sma[];
    const int t    = threadIdx.x;
    const int wid  = t >> 5;
    const int lane = t & 31;
    const int bh   = blockIdx.y;
    const int q0   = blockIdx.x * 64;

    const uint32_t smb = smem_u32(sma);
    const int lr = lane & 7;
    const uint32_t aOff = (uint32_t)((lr + ((lane >> 3) & 1) * 8) * 144
                                     + (lane >> 4) * 16);
    const uint32_t bOff = (uint32_t)((lr + ((lane >> 4) & 1) * 8) * 144
                                     + ((lane >> 3) & 1) * 16);

    // ---- Stage Q tile (64x64 hi/lo) into buf0 via cp.async ----
#pragma unroll
    for (int j = 0; j < 8; j++) {
        int gi   = t + j * 128;          // 0..1023
        int half = gi >> 9;              // 0 = hi, 1 = lo
        int idx  = gi & 511;
        int row  = idx >> 3;
        int c8   = idx & 7;
        const __nv_bfloat16* src =
            (half ? g_Ql : g_Qh) + (size_t)(bh * Ss + q0 + row) * HD + c8 * 8;
        cpa16(smb + half * (2 * ASEC) + row * 144 + c8 * 16, src);
    }
    CP_COMMIT();
    CP_WAIT0();
    __syncthreads();

    uint32_t qh[4][4], ql[4][4];
#pragma unroll
    for (int kt2 = 0; kt2 < 4; kt2++) {
        uint32_t ad = smb + (uint32_t)(wid * 16 * 144) + aOff + kt2 * 32;
        ldm_x4(ad,             qh[kt2][0], qh[kt2][1], qh[kt2][2], qh[kt2][3]);
        ldm_x4(ad + 2 * ASEC,  ql[kt2][0], ql[kt2][1], ql[kt2][2], ql[kt2][3]);
    }
    __syncthreads();   // buf0 free for KV

    float o[8][4];
#pragma unroll
    for (int j = 0; j < 8; j++)
#pragma unroll
        for (int v = 0; v < 4; v++) o[j][v] = 0.f;
    float m0r = -1e30f, m1r = -1e30f, l0r = 0.f, l1r = 0.f;

    // Issue one KV tile: 4 sections x 64 rows x 8 x 16B = 16 cp.async/thread.
    auto issue_tile = [&](int kt, int buf) {
        const uint32_t base = smb + buf * ABUF;
#pragma unroll
        for (int j = 0; j < 16; j++) {
            int gi  = t + j * 128;       // 0..2047
            int sec = gi >> 9;           // 0..3
            int idx = gi & 511;
            int row = idx >> 3;
            int c8  = idx & 7;
            const __nv_bfloat16* src;
            if (sec == 0)      src = g_Kh  + (size_t)(bh * Ss + kt + row) * HD + c8 * 8;
            else if (sec == 1) src = g_Kl  + (size_t)(bh * Ss + kt + row) * HD + c8 * 8;
            else if (sec == 2) src = g_Vth + (size_t)(bh * HD + row) * Ss + kt + c8 * 8;
            else               src = g_Vtl + (size_t)(bh * HD + row) * Ss + kt + c8 * 8;
            cpa16(base + sec * ASEC + row * 144 + c8 * 16, src);
        }
        CP_COMMIT();
    };

    issue_tile(0, 0);

    const float L2E = 1.44269504f;

    for (int ti = 0; ti < NKT; ti++) {
        const int cur = ti & 1;
        if (ti + 1 < NKT) { issue_tile((ti + 1) * 64, 1 - cur); CP_WAIT1(); }
        else              { CP_WAIT0(); }
        __syncthreads();

        const uint32_t bb = smb + cur * ABUF;

        // ---- S = Qs . K^T  (3-term split) ----
        float s[8][4];
#pragma unroll
        for (int j = 0; j < 8; j++)
#pragma unroll
            for (int v = 0; v < 4; v++) s[j][v] = 0.f;

#pragma unroll
        for (int ks2 = 0; ks2 < 4; ks2++) {
            uint32_t kh[4][4], kl_[4][4];
#pragma unroll
            for (int u = 0; u < 4; u++) {
                uint32_t ad = bb + (uint32_t)(u * 16 * 144) + bOff + ks2 * 32;
                ldm_x4(ad,        kh[u][0], kh[u][1], kh[u][2], kh[u][3]);
                ldm_x4(ad + ASEC, kl_[u][0], kl_[u][1], kl_[u][2], kl_[u][3]);
            }
#pragma unroll
            for (int j = 0; j < 8; j++) {
                int u = j >> 1, od = (j & 1) * 2;
                mma16816(s[j], qh[ks2], kh[u][od], kh[u][od + 1]);
                mma16816(s[j], qh[ks2], kl_[u][od], kl_[u][od + 1]);
                mma16816(s[j], ql[ks2], kh[u][od], kh[u][od + 1]);
            }
        }

        // ---- Online softmax (warp-local; fused exp2) ----
        float rmx0 = -1e30f, rmx1 = -1e30f;
#pragma unroll
        for (int j = 0; j < 8; j++) {
            rmx0 = fmaxf(rmx0, fmaxf(s[j][0], s[j][1]));
            rmx1 = fmaxf(rmx1, fmaxf(s[j][2], s[j][3]));
        }
        rmx0 = fmaxf(rmx0, __shfl_xor_sync(0xffffffffu, rmx0, 1));
        rmx0 = fmaxf(rmx0, __shfl_xor_sync(0xffffffffu, rmx0, 2));
        rmx1 = fmaxf(rmx1, __shfl_xor_sync(0xffffffffu, rmx1, 1));
        rmx1 = fmaxf(rmx1, __shfl_xor_sync(0xffffffffu, rmx1, 2));

        float mn0 = fmaxf(m0r, rmx0), mn1 = fmaxf(m1r, rmx1);
        float a0 = ex2f((m0r - mn0) * L2E), a1 = ex2f((m1r - mn1) * L2E);
        m0r = mn0; m1r = mn1;
        const float nb0 = -mn0 * L2E, nb1 = -mn1 * L2E;

        float rs0 = 0.f, rs1 = 0.f;
#pragma unroll
        for (int j = 0; j < 8; j++) {
            s[j][0] = ex2f(fmaf(s[j][0], L2E, nb0));
            s[j][1] = ex2f(fmaf(s[j][1], L2E, nb0));
            s[j][2] = ex2f(fmaf(s[j][2], L2E, nb1));
            s[j][3] = ex2f(fmaf(s[j][3], L2E, nb1));
            rs0 += s[j][0] + s[j][1];
            rs1 += s[j][2] + s[j][3];
        }
        rs0 += __shfl_xor_sync(0xffffffffu, rs0, 1);
        rs0 += __shfl_xor_sync(0xffffffffu, rs0, 2);
        rs1 += __shfl_xor_sync(0xffffffffu, rs1, 1);
        rs1 += __shfl_xor_sync(0xffffffffu, rs1, 2);
        l0r = l0r * a0 + rs0;
        l1r = l1r * a1 + rs1;
#pragma unroll
        for (int j = 0; j < 8; j++) {
            o[j][0] *= a0; o[j][1] *= a0;
            o[j][2] *= a1; o[j][3] *= a1;
        }

        // ---- Pack P into A-fragments (truncation split, registers) ----
        uint32_t ph[4][4], pl_[4][4];
#pragma unroll
        for (int ks2 = 0; ks2 < 4; ks2++) {
            int j0 = 2 * ks2, j1 = 2 * ks2 + 1;
            splitP(s[j0][0], s[j0][1], ph[ks2][0], pl_[ks2][0]);
            splitP(s[j0][2], s[j0][3], ph[ks2][1], pl_[ks2][1]);
            splitP(s[j1][0], s[j1][1], ph[ks2][2], pl_[ks2][2]);
            splitP(s[j1][2], s[j1][3], ph[ks2][3], pl_[ks2][3]);
        }

        // ---- O += P . V  (3-term split) ----
#pragma unroll
        for (int ks2 = 0; ks2 < 4; ks2++) {
            uint32_t vh[4][4], vl_[4][4];
#pragma unroll
            for (int u = 0; u < 4; u++) {
                uint32_t ad = bb + 2 * ASEC + (uint32_t)(u * 16 * 144) + bOff + ks2 * 32;
                ldm_x4(ad,        vh[u][0], vh[u][1], vh[u][2], vh[u][3]);
                ldm_x4(ad + ASEC, vl_[u][0], vl_[u][1], vl_[u][2], vl_[u][3]);
            }
#pragma unroll
            for (int j = 0; j < 8; j++) {
                int u = j >> 1, od = (j & 1) * 2;
                mma16816(o[j], ph[ks2], vh[u][od], vh[u][od + 1]);
                mma16816(o[j], pl_[ks2], vh[u][od], vh[u][od + 1]);
                mma16816(o[j], ph[ks2], vl_[u][od], vl_[u][od + 1]);
            }
        }
        __syncthreads();   // next issue overwrites buf[1-cur]
    }

    // ---- Epilogue ----
    const int g  = lane >> 2;
    const int tc = (lane & 3) * 2;
    const int bb2 = bh >> 4;
    const int hh  = bh & 15;
    const float i0 = 1.0f / l0r, i1 = 1.0f / l1r;
    const int q  = q0 + wid * 16 + g;
#pragma unroll
    for (int j = 0; j < 8; j++) {
        int d = j * 8 + tc;
        size_t off0 = ((size_t)(bb2 * Ss + q)) * Ee + hh * 64 + d;
        size_t off1 = ((size_t)(bb2 * Ss + q + 8)) * Ee + hh * 64 + d;
        *(float2*)(Out + off0) = make_float2(o[j][0] * i0, o[j][1] * i0);
        *(float2*)(Out + off1) = make_float2(o[j][2] * i1, o[j][3] * i1);
    }
}

// ---------------------------------------------------------------------------
extern "C" void kernel_launch(void* const* d_in, const int* in_sizes, int n_in,
                              void* d_out, int out_size)
{
    const float* x  = (const float*)d_in[0];
    const float* Wq = (const float*)d_in[1];
    const float* Wk = (const float*)d_in[2];
    const float* Wv = (const float*)d_in[3];
    float* out = (float*)d_out;

    static bool attr_done = false;
    if (!attr_done) {
        cudaFuncSetAttribute(proj_tc, cudaFuncAttributeMaxDynamicSharedMemorySize,
                             PROJ_SMEM);
        cudaFuncSetAttribute(attn_tc, cudaFuncAttributeMaxDynamicSharedMemorySize,
                             ATTN_SMEM);
        attr_done = true;
    }

    split_xw<<<2048, 256>>>(x, Wq, Wk, Wv);

    dim3 pgrid(Ee / 128, (Bn * Ss) / 128, 3);   // (8, 64, 3)
    proj_tc<<<pgrid, 256, PROJ_SMEM>>>();

    dim3 agrid(Ss / 64, Bn * Hh);               // (32, 64)
    attn_tc<<<agrid, 128, ATTN_SMEM>>>(out);
}

// round 13
// speedup vs baseline: 4.1355x; 1.1787x over previous
#include <cuda_runtime.h>
#include <cuda_bf16.h>
#include <cuda_fp16.h>
#include <cstdint>

#define Bn 4
#define Ss 2048
#define Ee 1024
#define Hh 16
#define HD 64

// Pre-split bf16 inputs (filled by split_xw)
__device__ __align__(16) __nv_bfloat16 g_Xh[(size_t)Bn * Ss * Ee];
__device__ __align__(16) __nv_bfloat16 g_Xl[(size_t)Bn * Ss * Ee];
__device__ __align__(16) __nv_bfloat16 g_Wh[(size_t)3 * Ee * Ee];
__device__ __align__(16) __nv_bfloat16 g_Wl[(size_t)3 * Ee * Ee];

// fp16 attention operands (Q pre-scaled by 1/32). Q/K: [b,h,s,d]; V: [b,h,d,s].
// Q,K single fp16; V fp16 hi + fp16 residual lo.
__device__ __align__(16) __half g_Qh[(size_t)Bn * Hh * Ss * HD];
__device__ __align__(16) __half g_Kh[(size_t)Bn * Hh * Ss * HD];
__device__ __align__(16) __half g_Vth[(size_t)Bn * Hh * Ss * HD];
__device__ __align__(16) __half g_Vtl[(size_t)Bn * Hh * Ss * HD];

// ===========================================================================
// Helpers
// ===========================================================================
__device__ __forceinline__ uint32_t smem_u32(const void* p) {
    uint32_t a;
    asm("{ .reg .u64 t; cvta.to.shared.u64 t, %1; cvt.u32.u64 %0, t; }"
        : "=r"(a) : "l"(p));
    return a;
}

__device__ __forceinline__ void ldm_x4(uint32_t addr, uint32_t& r0, uint32_t& r1,
                                       uint32_t& r2, uint32_t& r3) {
    asm volatile("ldmatrix.sync.aligned.m8n8.x4.shared.b16 {%0,%1,%2,%3}, [%4];"
                 : "=r"(r0), "=r"(r1), "=r"(r2), "=r"(r3) : "r"(addr));
}

// bf16 MMA (projection path)
__device__ __forceinline__ void mma16816(float* d, const uint32_t* a,
                                         uint32_t b0, uint32_t b1) {
    asm volatile(
        "mma.sync.aligned.m16n8k16.row.col.f32.bf16.bf16.f32 "
        "{%0,%1,%2,%3}, {%4,%5,%6,%7}, {%8,%9}, {%0,%1,%2,%3};"
        : "+f"(d[0]), "+f"(d[1]), "+f"(d[2]), "+f"(d[3])
        : "r"(a[0]), "r"(a[1]), "r"(a[2]), "r"(a[3]), "r"(b0), "r"(b1));
}

// fp16 MMA (attention path)
__device__ __forceinline__ void mma16816h(float* d, const uint32_t* a,
                                          uint32_t b0, uint32_t b1) {
    asm volatile(
        "mma.sync.aligned.m16n8k16.row.col.f32.f16.f16.f32 "
        "{%0,%1,%2,%3}, {%4,%5,%6,%7}, {%8,%9}, {%0,%1,%2,%3};"
        : "+f"(d[0]), "+f"(d[1]), "+f"(d[2]), "+f"(d[3])
        : "r"(a[0]), "r"(a[1]), "r"(a[2]), "r"(a[3]), "r"(b0), "r"(b1));
}

__device__ __forceinline__ void cpa16(uint32_t dst, const void* src) {
    asm volatile("cp.async.cg.shared.global [%0], [%1], 16;"
                 :: "r"(dst), "l"(src) : "memory");
}
#define CP_COMMIT() asm volatile("cp.async.commit_group;" ::: "memory")
#define CP_WAIT0()  asm volatile("cp.async.wait_group 0;" ::: "memory")
#define CP_WAIT1()  asm volatile("cp.async.wait_group 1;" ::: "memory")

__device__ __forceinline__ float ex2f(float x) {
    float r;
    asm("ex2.approx.ftz.f32 %0, %1;" : "=f"(r) : "f"(x));
    return r;
}

// fp32 pair -> bf16x2 hi + bf16x2 lo (residual)
__device__ __forceinline__ void split2(float x, float y, uint32_t& hi, uint32_t& lo) {
    __nv_bfloat162 h = __floats2bfloat162_rn(x, y);
    float2 f = __bfloat1622float2(h);
    __nv_bfloat162 l = __floats2bfloat162_rn(x - f.x, y - f.y);
    hi = *reinterpret_cast<uint32_t*>(&h);
    lo = *reinterpret_cast<uint32_t*>(&l);
}

// fp32 pair -> fp16x2 hi + fp16x2 lo (residual)
__device__ __forceinline__ void splitPh(float x, float y, uint32_t& hi, uint32_t& lo) {
    __half2 h = __floats2half2_rn(x, y);
    float2 f = __half22float2(h);
    __half2 l = __floats2half2_rn(x - f.x, y - f.y);
    hi = *reinterpret_cast<uint32_t*>(&h);
    lo = *reinterpret_cast<uint32_t*>(&l);
}

// ===========================================================================
// Pre-pass: split X and W into bf16 hi/lo (~18 us).
// ===========================================================================
__global__ void split_xw(const float* __restrict__ x, const float* __restrict__ wq,
                         const float* __restrict__ wk, const float* __restrict__ wv)
{
    const int XN2 = (Bn * Ss * Ee) / 2;
    const int WN2 = (Ee * Ee) / 2;
    const int total = XN2 + 3 * WN2;
    for (int i = blockIdx.x * blockDim.x + threadIdx.x; i < total;
         i += gridDim.x * blockDim.x) {
        float2 v;
        uint32_t hi, lo;
        if (i < XN2) {
            v = reinterpret_cast<const float2*>(x)[i];
            split2(v.x, v.y, hi, lo);
            reinterpret_cast<uint32_t*>(g_Xh)[i] = hi;
            reinterpret_cast<uint32_t*>(g_Xl)[i] = lo;
        } else {
            int r = i - XN2;
            int w = r / WN2;
            int j = r - w * WN2;
            const float* src = (w == 0) ? wq : (w == 1) ? wk : wv;
            v = reinterpret_cast<const float2*>(src)[j];
            split2(v.x, v.y, hi, lo);
            reinterpret_cast<uint32_t*>(g_Wh)[r] = hi;
            reinterpret_cast<uint32_t*>(g_Wl)[r] = lo;
        }
    }
}

// ===========================================================================
// Fused QKV projection: full 3-term bf16 split (R9-accurate), cp.async
// double-buffered, tile 128x128, BK=64. Epilogue emits fp16 Q/K/V.
// ===========================================================================
#define SECB 18432
#define STGB (4 * SECB)
#define PROJ_SMEM (2 * STGB)
#define NCHP 16

__global__ __launch_bounds__(256, 1)
void proj_tc()
{
    extern __shared__ __align__(16) char sm[];
    const int t    = threadIdx.x;
    const int wid  = t >> 5;
    const int lane = t & 31;
    const int n0   = blockIdx.x * 128;
    const int m0   = blockIdx.y * 128;
    const int z    = blockIdx.z;

    const __nv_bfloat16* __restrict__ Wh = g_Wh + (size_t)z * Ee * Ee;
    const __nv_bfloat16* __restrict__ Wl = g_Wl + (size_t)z * Ee * Ee;

    const int wm = (wid >> 1) * 32;
    const int wn = (wid & 1) * 64;
    const uint32_t smb = smem_u32(sm);

    const int lr = lane & 7;
    const uint32_t aRowOff = (uint32_t)((lr + ((lane >> 3) & 1) * 8) * 144
                                        + (lane >> 4) * 16);
    const uint32_t bRowOff = (uint32_t)((lr + ((lane >> 4) & 1) * 8) * 144
                                        + ((lane >> 3) & 1) * 16);

    float acc[2][8][4];
#pragma unroll
    for (int i = 0; i < 2; i++)
#pragma unroll
        for (int j = 0; j < 8; j++)
#pragma unroll
            for (int v = 0; v < 4; v++) acc[i][j][v] = 0.f;

    auto issue_chunk = [&](int c, int stg) {
        const int k0 = c * 64;
        const uint32_t base = smb + stg * STGB;
#pragma unroll
        for (int j = 0; j < 16; j++) {
            int gi  = t + j * 256;
            int sec = gi >> 10;
            int idx = gi & 1023;
            int row = idx >> 3;
            int c8  = idx & 7;
            uint32_t dst = base + sec * SECB + row * 144 + c8 * 16;
            const __nv_bfloat16* src;
            if (sec == 0)      src = g_Xh + (size_t)(m0 + row) * Ee + k0 + c8 * 8;
            else if (sec == 1) src = g_Xl + (size_t)(m0 + row) * Ee + k0 + c8 * 8;
            else if (sec == 2) src = Wh + (size_t)(n0 + row) * Ee + k0 + c8 * 8;
            else               src = Wl + (size_t)(n0 + row) * Ee + k0 + c8 * 8;
            cpa16(dst, src);
        }
        CP_COMMIT();
    };

    issue_chunk(0, 0);

    for (int c = 0; c < NCHP; ++c) {
        const int cur = c & 1;
        if (c + 1 < NCHP) { issue_chunk(c + 1, 1 - cur); CP_WAIT1(); }
        else              { CP_WAIT0(); }
        __syncthreads();

        const uint32_t sb = smb + cur * STGB;
#pragma unroll
        for (int kt = 0; kt < 4; kt++) {
            const uint32_t kb = kt * 32;
            uint32_t ah[2][4], al[2][4], bh[4][4], bl[4][4];
#pragma unroll
            for (int mt = 0; mt < 2; mt++) {
                uint32_t ro = sb + (uint32_t)((wm + mt * 16) * 144) + aRowOff + kb;
                ldm_x4(ro,        ah[mt][0], ah[mt][1], ah[mt][2], ah[mt][3]);
                ldm_x4(ro + SECB, al[mt][0], al[mt][1], al[mt][2], al[mt][3]);
            }
#pragma unroll
            for (int u = 0; u < 4; u++) {
                uint32_t ro = sb + 2 * SECB + (uint32_t)((wn + u * 16) * 144)
                              + bRowOff + kb;
                ldm_x4(ro,        bh[u][0], bh[u][1], bh[u][2], bh[u][3]);
                ldm_x4(ro + SECB, bl[u][0], bl[u][1], bl[u][2], bl[u][3]);
            }
#pragma unroll
            for (int mt = 0; mt < 2; mt++)
#pragma unroll
                for (int nt = 0; nt < 8; nt++) {
                    uint32_t b0h = bh[nt >> 1][(nt & 1) * 2];
                    uint32_t b1h = bh[nt >> 1][(nt & 1) * 2 + 1];
                    uint32_t b0l = bl[nt >> 1][(nt & 1) * 2];
                    uint32_t b1l = bl[nt >> 1][(nt & 1) * 2 + 1];
                    mma16816(acc[mt][nt], ah[mt], b0h, b1h);
                    mma16816(acc[mt][nt], ah[mt], b0l, b1l);
                    mma16816(acc[mt][nt], al[mt], b0h, b1h);
                }
        }
        __syncthreads();
    }

    // Epilogue: Q,K -> single fp16 (Q scaled 1/32); V -> fp16 hi/lo, transposed.
    const int g  = lane >> 2;
    const int tc = (lane & 3) * 2;
    const float scl = (z == 0) ? (1.0f / 32.0f) : 1.0f;
#pragma unroll
    for (int mt = 0; mt < 2; mt++) {
#pragma unroll
        for (int half = 0; half < 2; half++) {
            int m  = m0 + wm + mt * 16 + g + half * 8;
            int bb = m >> 11;
            int sq = m & 2047;
#pragma unroll
            for (int nt = 0; nt < 8; nt++) {
                int n  = n0 + wn + nt * 8 + tc;
                int hh = n >> 6;
                int dd = n & 63;
                float v0 = acc[mt][nt][half * 2] * scl;
                float v1 = acc[mt][nt][half * 2 + 1] * scl;
                if (z == 2) {
                    size_t vb = (size_t)(bb * Hh + hh) * HD * Ss;
                    __half h0 = __float2half_rn(v0);
                    __half h1 = __float2half_rn(v1);
                    __half l0 = __float2half_rn(v0 - __half2float(h0));
                    __half l1 = __float2half_rn(v1 - __half2float(h1));
                    g_Vth[vb + (size_t)dd * Ss + sq]       = h0;
                    g_Vtl[vb + (size_t)dd * Ss + sq]       = l0;
                    g_Vth[vb + (size_t)(dd + 1) * Ss + sq] = h1;
                    g_Vtl[vb + (size_t)(dd + 1) * Ss + sq] = l1;
                } else {
                    __half2 h = __floats2half2_rn(v0, v1);
                    size_t off = ((size_t)(bb * Hh + hh) * Ss + sq) * HD + dd;
                    __half* dst = (z == 0) ? g_Qh : g_Kh;
                    *reinterpret_cast<uint32_t*>(dst + off) =
                        *reinterpret_cast<uint32_t*>(&h);
                }
            }
        }
    }
}

// ===========================================================================
// fp16 tensor-core flash attention. QK^T: SINGLE fp16 MMA; PV: 3-term fp16.
// 128-thread CTAs (3/SM), 64 q-rows, 4 warps x 16 rows, warp-local softmax.
// KV buffers: 2 x (Kh|Vth|Vtl), each section 64 rows x 144 B.
// ===========================================================================
#define ASEC 9216
#define ABUF (3 * ASEC)          // 27648
#define ATTN_SMEM (2 * ABUF)     // 55296
#define NKT (Ss / 64)            // 32

__global__ __launch_bounds__(128, 3)
void attn_tc(float* __restrict__ Out)
{
    extern __shared__ __align__(16) char sma[];
    const int t    = threadIdx.x;
    const int wid  = t >> 5;
    const int lane = t & 31;
    const int bh   = blockIdx.y;
    const int q0   = blockIdx.x * 64;

    const uint32_t smb = smem_u32(sma);
    const int lr = lane & 7;
    const uint32_t aOff = (uint32_t)((lr + ((lane >> 3) & 1) * 8) * 144
                                     + (lane >> 4) * 16);
    const uint32_t bOff = (uint32_t)((lr + ((lane >> 4) & 1) * 8) * 144
                                     + ((lane >> 3) & 1) * 16);

    // ---- Stage Q tile (64x64 fp16) into buf0 via cp.async ----
#pragma unroll
    for (int j = 0; j < 4; j++) {
        int gi  = t + j * 128;           // 0..511
        int row = gi >> 3;
        int c8  = gi & 7;
        const __half* src = g_Qh + (size_t)(bh * Ss + q0 + row) * HD + c8 * 8;
        cpa16(smb + row * 144 + c8 * 16, src);
    }
    CP_COMMIT();
    CP_WAIT0();
    __syncthreads();

    uint32_t qh[4][4];
#pragma unroll
    for (int kt2 = 0; kt2 < 4; kt2++) {
        uint32_t ad = smb + (uint32_t)(wid * 16 * 144) + aOff + kt2 * 32;
        ldm_x4(ad, qh[kt2][0], qh[kt2][1], qh[kt2][2], qh[kt2][3]);
    }
    __syncthreads();   // buf0 free for KV

    float o[8][4];
#pragma unroll
    for (int j = 0; j < 8; j++)
#pragma unroll
        for (int v = 0; v < 4; v++) o[j][v] = 0.f;
    float m0r = -1e30f, m1r = -1e30f, l0r = 0.f, l1r = 0.f;

    // Issue one KV tile: 3 sections x 64 rows x 8 x 16B = 12 cp.async/thread.
    auto issue_tile = [&](int kt, int buf) {
        const uint32_t base = smb + buf * ABUF;
#pragma unroll
        for (int j = 0; j < 12; j++) {
            int gi  = t + j * 128;       // 0..1535
            int sec = gi >> 9;           // 0..2
            int idx = gi & 511;
            int row = idx >> 3;
            int c8  = idx & 7;
            const __half* src;
            if (sec == 0)      src = g_Kh  + (size_t)(bh * Ss + kt + row) * HD + c8 * 8;
            else if (sec == 1) src = g_Vth + (size_t)(bh * HD + row) * Ss + kt + c8 * 8;
            else               src = g_Vtl + (size_t)(bh * HD + row) * Ss + kt + c8 * 8;
            cpa16(base + sec * ASEC + row * 144 + c8 * 16, src);
        }
        CP_COMMIT();
    };

    issue_tile(0, 0);

    const float L2E = 1.44269504f;

    for (int ti = 0; ti < NKT; ti++) {
        const int cur = ti & 1;
        if (ti + 1 < NKT) { issue_tile((ti + 1) * 64, 1 - cur); CP_WAIT1(); }
        else              { CP_WAIT0(); }
        __syncthreads();

        const uint32_t bb = smb + cur * ABUF;

        // ---- S = Q . K^T  (single fp16 MMA per atom) ----
        float s[8][4];
#pragma unroll
        for (int j = 0; j < 8; j++)
#pragma unroll
            for (int v = 0; v < 4; v++) s[j][v] = 0.f;

#pragma unroll
        for (int ks2 = 0; ks2 < 4; ks2++) {
            uint32_t kh[4][4];
#pragma unroll
            for (int u = 0; u < 4; u++) {
                uint32_t ad = bb + (uint32_t)(u * 16 * 144) + bOff + ks2 * 32;
                ldm_x4(ad, kh[u][0], kh[u][1], kh[u][2], kh[u][3]);
            }
#pragma unroll
            for (int j = 0; j < 8; j++) {
                int u = j >> 1, od = (j & 1) * 2;
                mma16816h(s[j], qh[ks2], kh[u][od], kh[u][od + 1]);
            }
        }

        // ---- Online softmax (warp-local; fused exp2) ----
        float rmx0 = -1e30f, rmx1 = -1e30f;
#pragma unroll
        for (int j = 0; j < 8; j++) {
            rmx0 = fmaxf(rmx0, fmaxf(s[j][0], s[j][1]));
            rmx1 = fmaxf(rmx1, fmaxf(s[j][2], s[j][3]));
        }
        rmx0 = fmaxf(rmx0, __shfl_xor_sync(0xffffffffu, rmx0, 1));
        rmx0 = fmaxf(rmx0, __shfl_xor_sync(0xffffffffu, rmx0, 2));
        rmx1 = fmaxf(rmx1, __shfl_xor_sync(0xffffffffu, rmx1, 1));
        rmx1 = fmaxf(rmx1, __shfl_xor_sync(0xffffffffu, rmx1, 2));

        float mn0 = fmaxf(m0r, rmx0), mn1 = fmaxf(m1r, rmx1);
        float a0 = ex2f((m0r - mn0) * L2E), a1 = ex2f((m1r - mn1) * L2E);
        m0r = mn0; m1r = mn1;
        const float nb0 = -mn0 * L2E, nb1 = -mn1 * L2E;

        float rs0 = 0.f, rs1 = 0.f;
#pragma unroll
        for (int j = 0; j < 8; j++) {
            s[j][0] = ex2f(fmaf(s[j][0], L2E, nb0));
            s[j][1] = ex2f(fmaf(s[j][1], L2E, nb0));
            s[j][2] = ex2f(fmaf(s[j][2], L2E, nb1));
            s[j][3] = ex2f(fmaf(s[j][3], L2E, nb1));
            rs0 += s[j][0] + s[j][1];
            rs1 += s[j][2] + s[j][3];
        }
        rs0 += __shfl_xor_sync(0xffffffffu, rs0, 1);
        rs0 += __shfl_xor_sync(0xffffffffu, rs0, 2);
        rs1 += __shfl_xor_sync(0xffffffffu, rs1, 1);
        rs1 += __shfl_xor_sync(0xffffffffu, rs1, 2);
        l0r = l0r * a0 + rs0;
        l1r = l1r * a1 + rs1;
#pragma unroll
        for (int j = 0; j < 8; j++) {
            o[j][0] *= a0; o[j][1] *= a0;
            o[j][2] *= a1; o[j][3] *= a1;
        }

        // ---- Pack P into fp16 A-fragments (hi + exact-residual lo) ----
        uint32_t ph[4][4], pl_[4][4];
#pragma unroll
        for (int ks2 = 0; ks2 < 4; ks2++) {
            int j0 = 2 * ks2, j1 = 2 * ks2 + 1;
            splitPh(s[j0][0], s[j0][1], ph[ks2][0], pl_[ks2][0]);
            splitPh(s[j0][2], s[j0][3], ph[ks2][1], pl_[ks2][1]);
            splitPh(s[j1][0], s[j1][1], ph[ks2][2], pl_[ks2][2]);
            splitPh(s[j1][2], s[j1][3], ph[ks2][3], pl_[ks2][3]);
        }

        // ---- O += P . V  (3-term fp16) ----
#pragma unroll
        for (int ks2 = 0; ks2 < 4; ks2++) {
            uint32_t vh[4][4], vl_[4][4];
#pragma unroll
            for (int u = 0; u < 4; u++) {
                uint32_t ad = bb + ASEC + (uint32_t)(u * 16 * 144) + bOff + ks2 * 32;
                ldm_x4(ad,        vh[u][0], vh[u][1], vh[u][2], vh[u][3]);
                ldm_x4(ad + ASEC, vl_[u][0], vl_[u][1], vl_[u][2], vl_[u][3]);
            }
#pragma unroll
            for (int j = 0; j < 8; j++) {
                int u = j >> 1, od = (j & 1) * 2;
                mma16816h(o[j], ph[ks2], vh[u][od], vh[u][od + 1]);
                mma16816h(o[j], pl_[ks2], vh[u][od], vh[u][od + 1]);
                mma16816h(o[j], ph[ks2], vl_[u][od], vl_[u][od + 1]);
            }
        }
        __syncthreads();   // next issue overwrites buf[1-cur]
    }

    // ---- Epilogue ----
    const int g  = lane >> 2;
    const int tc = (lane & 3) * 2;
    const int bb2 = bh >> 4;
    const int hh  = bh & 15;
    const float i0 = 1.0f / l0r, i1 = 1.0f / l1r;
    const int q  = q0 + wid * 16 + g;
#pragma unroll
    for (int j = 0; j < 8; j++) {
        int d = j * 8 + tc;
        size_t off0 = ((size_t)(bb2 * Ss + q)) * Ee + hh * 64 + d;
        size_t off1 = ((size_t)(bb2 * Ss + q + 8)) * Ee + hh * 64 + d;
        *(float2*)(Out + off0) = make_float2(o[j][0] * i0, o[j][1] * i0);
        *(float2*)(Out + off1) = make_float2(o[j][2] * i1, o[j][3] * i1);
    }
}

// ---------------------------------------------------------------------------
extern "C" void kernel_launch(void* const* d_in, const int* in_sizes, int n_in,
                              void* d_out, int out_size)
{
    const float* x  = (const float*)d_in[0];
    const float* Wq = (const float*)d_in[1];
    const float* Wk = (const float*)d_in[2];
    const float* Wv = (const float*)d_in[3];
    float* out = (float*)d_out;

    static bool attr_done = false;
    if (!attr_done) {
        cudaFuncSetAttribute(proj_tc, cudaFuncAttributeMaxDynamicSharedMemorySize,
                             PROJ_SMEM);
        cudaFuncSetAttribute(attn_tc, cudaFuncAttributeMaxDynamicSharedMemorySize,
                             ATTN_SMEM);
        attr_done = true;
    }

    split_xw<<<2048, 256>>>(x, Wq, Wk, Wv);

    dim3 pgrid(Ee / 128, (Bn * Ss) / 128, 3);   // (8, 64, 3)
    proj_tc<<<pgrid, 256, PROJ_SMEM>>>();

    dim3 agrid(Ss / 64, Bn * Hh);               // (32, 64)
    attn_tc<<<agrid, 128, ATTN_SMEM>>>(out);
}